// round 5
// baseline (speedup 1.0000x reference)
#include <cuda_runtime.h>
#include <cuda_bf16.h>
#include <cstdint>
#include <math.h>

#define BQ   32
#define TT   128
#define EE   256
#define HH   512
#define ENCC 512
#define VV   10000
#define G4   2048          // 4*H
#define XW   1280          // E + H + ENC
#define VPAD 10112         // 79 * 128

// ------------------------------------------------------------------
// scratch (static device globals; no allocations allowed)
// ------------------------------------------------------------------
__device__ float g_o[BQ * HH];
__device__ float g_c0[BQ * HH];
__device__ float g_base[BQ * G4];
__device__ float g_G[TT * BQ * G4];               // per-step gate input (32 MB)
__device__ float g_hs[(TT + 1) * BQ * HH];        // slot0=h0, slot t+1 = h after step t
__device__ unsigned g_bar_count;
__device__ unsigned g_bar_gen;

// bf16 hi/lo split operands for the tensor-core logits GEMM
__device__ __nv_bfloat16 g_Ahi[TT * BQ * HH];     // 4 MB
__device__ __nv_bfloat16 g_Alo[TT * BQ * HH];
__device__ __nv_bfloat16 g_Bhi[VPAD * HH];        // 10 MB (zero-padded rows)
__device__ __nv_bfloat16 g_Blo[VPAD * HH];

// ------------------------------------------------------------------
// kernel 1: o, h0, c0   (warp per output, shuffle reduce)
// ------------------------------------------------------------------
__global__ void k_init(const float* __restrict__ tv,
                       const float* __restrict__ Wo, const float* __restrict__ bo,
                       const float* __restrict__ Wh, const float* __restrict__ bh,
                       const float* __restrict__ Wc, const float* __restrict__ bc)
{
    int warp = (blockIdx.x * blockDim.x + threadIdx.x) >> 5;
    int lane = threadIdx.x & 31;
    if (warp >= 3 * BQ * HH) return;
    int m   = warp / (BQ * HH);
    int rem = warp % (BQ * HH);
    int b = rem / HH, j = rem % HH;
    const float* W    = (m == 0) ? Wo : (m == 1) ? Wh : Wc;
    const float* bias = (m == 0) ? bo : (m == 1) ? bh : bc;
    const float* x = tv + b * ENCC;
    const float* w = W  + j * ENCC;
    float s = 0.f;
    for (int k = lane; k < ENCC; k += 32) s += x[k] * w[k];
    #pragma unroll
    for (int o = 16; o; o >>= 1) s += __shfl_xor_sync(0xffffffffu, s, o);
    if (lane == 0) {
        float v = s + bias[j];
        if (m == 0)      g_o[b * HH + j]  = v;
        else if (m == 1) g_hs[b * HH + j] = v;   // slot 0 = h0
        else             g_c0[b * HH + j] = v;
    }
}

// ------------------------------------------------------------------
// kernel 2: gates_base
// ------------------------------------------------------------------
__global__ void k_base(const float* __restrict__ tv,
                       const float* __restrict__ W_ih,
                       const float* __restrict__ b_ih,
                       const float* __restrict__ b_hh)
{
    int warp = (blockIdx.x * blockDim.x + threadIdx.x) >> 5;
    int lane = threadIdx.x & 31;
    if (warp >= BQ * G4) return;
    int b = warp / G4, n = warp % G4;
    const float* w = W_ih + (size_t)n * XW + EE;
    float s = 0.f;
    for (int k = lane; k < HH + ENCC; k += 32) {
        float x = (k < HH) ? g_o[b * HH + k] : tv[b * ENCC + (k - HH)];
        s += x * w[k];
    }
    #pragma unroll
    for (int o = 16; o; o >>= 1) s += __shfl_xor_sync(0xffffffffu, s, o);
    if (lane == 0) g_base[b * G4 + n] = s + b_ih[n] + b_hh[n];
}

// ------------------------------------------------------------------
// kernel 3: G[t][b][n] = emb[token(t-1)] @ W_ih[:, :E]^T + gates_base
// ------------------------------------------------------------------
#define GM 64
#define GN 64
#define GK 16
__global__ void __launch_bounds__(256) k_G(const float* __restrict__ emb,
                                           const int*   __restrict__ texts,
                                           const int*   __restrict__ startp,
                                           const float* __restrict__ W_ih)
{
    __shared__ float As[GK][GM + 4];
    __shared__ float Bs[GK][GN + 4];
    __shared__ int   rowoff[GM];
    int tid = threadIdx.x;
    int nt = blockIdx.x, mt = blockIdx.y;

    if (tid < GM) {
        int r = mt * GM + tid;
        int t = r >> 5, b = r & 31;
        int tok = (t == 0) ? startp[0] : texts[b * TT + t - 1];
        rowoff[tid] = tok * EE;
    }
    __syncthreads();

    int tm = tid >> 4, tn = tid & 15;
    int lrow = tid >> 2;
    int lk   = (tid & 3) * 4;
    float acc[4][4] = {};

    for (int k0 = 0; k0 < EE; k0 += GK) {
        float4 av = *(const float4*)(emb + rowoff[lrow] + k0 + lk);
        float4 bv = *(const float4*)(W_ih + (size_t)(nt * GN + lrow) * XW + k0 + lk);
        __syncthreads();
        As[lk + 0][lrow] = av.x; As[lk + 1][lrow] = av.y;
        As[lk + 2][lrow] = av.z; As[lk + 3][lrow] = av.w;
        Bs[lk + 0][lrow] = bv.x; Bs[lk + 1][lrow] = bv.y;
        Bs[lk + 2][lrow] = bv.z; Bs[lk + 3][lrow] = bv.w;
        __syncthreads();
        #pragma unroll
        for (int kk = 0; kk < GK; kk++) {
            float4 a4 = *(const float4*)&As[kk][tm * 4];
            float4 b4 = *(const float4*)&Bs[kk][tn * 4];
            float ar[4] = {a4.x, a4.y, a4.z, a4.w};
            float br[4] = {b4.x, b4.y, b4.z, b4.w};
            #pragma unroll
            for (int i = 0; i < 4; i++)
                #pragma unroll
                for (int j = 0; j < 4; j++)
                    acc[i][j] = fmaf(ar[i], br[j], acc[i][j]);
        }
    }
    #pragma unroll
    for (int i = 0; i < 4; i++) {
        int r = mt * GM + tm * 4 + i;
        int ncol = nt * GN + tn * 4;
        float4 bs = *(const float4*)&g_base[(r & 31) * G4 + ncol];
        float4 v;
        v.x = acc[i][0] + bs.x; v.y = acc[i][1] + bs.y;
        v.z = acc[i][2] + bs.z; v.w = acc[i][3] + bs.w;
        *(float4*)&g_G[(size_t)r * G4 + ncol] = v;
    }
}

// ------------------------------------------------------------------
// kernel 4: sequential LSTM (persistent, 128 CTAs, grid barrier per step)
// ------------------------------------------------------------------
__global__ void __launch_bounds__(256, 1) k_lstm(const float* __restrict__ W_hh)
{
    extern __shared__ float smem[];
    float*  sW    = smem;
    float4* sW4   = (float4*)sW;
    float*  sH    = smem + 16 * 512;
    float4* sH4   = (float4*)sH;
    float*  sGate = sH + 64 * 32 * 4;
    float*  sC    = sGate + 16 * 32;
    __shared__ unsigned sGen;

    int tid = threadIdx.x;
    int p   = blockIdx.x;
    int b   = tid & 31;
    int rr  = tid >> 5;
    int lr0 = rr, lr1 = rr + 8;
    int n0 = (lr0 >> 2) * HH + p * 4 + (lr0 & 3);
    int n1 = (lr1 >> 2) * HH + p * 4 + (lr1 & 3);

    for (int idx = tid; idx < 16 * 128; idx += 256) {
        int lr = idx >> 7, k4 = idx & 127;
        int n  = (lr >> 2) * HH + p * 4 + (lr & 3);
        sW4[lr * 128 + k4] = *(const float4*)(W_hh + (size_t)n * HH + k4 * 4);
    }
    if (tid < 128) {
        int q = tid >> 5, b2 = tid & 31;
        sC[q * 32 + b2] = g_c0[b2 * HH + p * 4 + q];
    }
    if (tid == 0) sGen = g_bar_gen;
    __syncthreads();
    unsigned base_gen = sGen;

    for (int t = 0; t < TT; t++) {
        const float* hprev = g_hs + (size_t)t * (BQ * HH);
        float4 accA = {0, 0, 0, 0}, accB = {0, 0, 0, 0};
        #pragma unroll
        for (int half = 0; half < 2; half++) {
            for (int idx = tid; idx < 64 * 32; idx += 256) {
                int k4 = idx >> 5, bb = idx & 31;
                sH4[idx] = __ldcg((const float4*)(hprev + bb * HH + half * 256 + k4 * 4));
            }
            __syncthreads();
            const float4* wA = sW4 + lr0 * 128 + half * 64;
            const float4* wB = sW4 + lr1 * 128 + half * 64;
            #pragma unroll 4
            for (int k4 = 0; k4 < 64; k4++) {
                float4 h4 = sH4[k4 * 32 + b];
                float4 a  = wA[k4];
                float4 c  = wB[k4];
                accA.x = fmaf(h4.x, a.x, accA.x);
                accA.y = fmaf(h4.y, a.y, accA.y);
                accA.z = fmaf(h4.z, a.z, accA.z);
                accA.w = fmaf(h4.w, a.w, accA.w);
                accB.x = fmaf(h4.x, c.x, accB.x);
                accB.y = fmaf(h4.y, c.y, accB.y);
                accB.z = fmaf(h4.z, c.z, accB.z);
                accB.w = fmaf(h4.w, c.w, accB.w);
            }
            __syncthreads();
        }
        float gA = (accA.x + accA.y) + (accA.z + accA.w)
                 + g_G[(size_t)(t * BQ + b) * G4 + n0];
        float gB = (accB.x + accB.y) + (accB.z + accB.w)
                 + g_G[(size_t)(t * BQ + b) * G4 + n1];
        sGate[lr0 * 32 + b] = gA;
        sGate[lr1 * 32 + b] = gB;
        __syncthreads();
        if (tid < 128) {
            int q = tid >> 5, b2 = tid & 31;
            float ig = sGate[(q     ) * 32 + b2];
            float fg = sGate[(4  + q) * 32 + b2];
            float gg = sGate[(8  + q) * 32 + b2];
            float og = sGate[(12 + q) * 32 + b2];
            float iS = 1.f / (1.f + expf(-ig));
            float fS = 1.f / (1.f + expf(-fg));
            float gT = tanhf(gg);
            float oS = 1.f / (1.f + expf(-og));
            float c  = fS * sC[q * 32 + b2] + iS * gT;
            sC[q * 32 + b2] = c;
            float h = oS * tanhf(c);
            g_hs[(size_t)(t + 1) * (BQ * HH) + b2 * HH + p * 4 + q] = h;
        }
        __threadfence();
        __syncthreads();
        if (tid == 0) {
            unsigned target = base_gen + (unsigned)(t + 1);
            unsigned arr = atomicAdd(&g_bar_count, 1u);
            if (arr == 127u) {
                g_bar_count = 0u;
                __threadfence();
                atomicExch(&g_bar_gen, target);
            } else {
                volatile unsigned* vg = &g_bar_gen;
                while (*vg < target) { }
            }
            __threadfence();
        }
        __syncthreads();
    }
}

// ------------------------------------------------------------------
// conversion kernels: fp32 -> bf16 hi/lo split
// ------------------------------------------------------------------
__global__ void k_convA()
{
    int idx = blockIdx.x * 256 + threadIdx.x;          // TT*BQ*HH = 2097152
    float x = g_hs[BQ * HH + idx];
    __nv_bfloat16 hi = __float2bfloat16(x);
    float r = x - __bfloat162float(hi);
    g_Ahi[idx] = hi;
    g_Alo[idx] = __float2bfloat16(r);
}

__global__ void k_convB(const float* __restrict__ Wv)
{
    size_t idx = (size_t)blockIdx.x * 256 + threadIdx.x;   // VPAD*HH
    int n = (int)(idx >> 9);
    float x = (n < VV) ? Wv[idx] : 0.f;
    __nv_bfloat16 hi = __float2bfloat16(x);
    float r = x - __bfloat162float(hi);
    g_Bhi[idx] = hi;
    g_Blo[idx] = __float2bfloat16(r);
}

// ------------------------------------------------------------------
// mma / ldmatrix / cp.async helpers
// ------------------------------------------------------------------
__device__ __forceinline__ void cp_async16(uint32_t dst, const void* src)
{
    asm volatile("cp.async.cg.shared.global [%0], [%1], 16;" :: "r"(dst), "l"(src));
}
__device__ __forceinline__ void cp_commit()
{
    asm volatile("cp.async.commit_group;");
}
__device__ __forceinline__ void ldsm_x4(uint32_t& r0, uint32_t& r1,
                                        uint32_t& r2, uint32_t& r3, uint32_t addr)
{
    asm volatile("ldmatrix.sync.aligned.m8n8.x4.shared.b16 {%0,%1,%2,%3}, [%4];"
                 : "=r"(r0), "=r"(r1), "=r"(r2), "=r"(r3) : "r"(addr));
}
__device__ __forceinline__ void ldsm_x2(uint32_t& r0, uint32_t& r1, uint32_t addr)
{
    asm volatile("ldmatrix.sync.aligned.m8n8.x2.shared.b16 {%0,%1}, [%2];"
                 : "=r"(r0), "=r"(r1) : "r"(addr));
}
__device__ __forceinline__ void mma16816(float& c0, float& c1, float& c2, float& c3,
                                         uint32_t a0, uint32_t a1, uint32_t a2, uint32_t a3,
                                         uint32_t b0, uint32_t b1)
{
    asm volatile("mma.sync.aligned.m16n8k16.row.col.f32.bf16.bf16.f32 "
                 "{%0,%1,%2,%3}, {%4,%5,%6,%7}, {%8,%9}, {%0,%1,%2,%3};"
                 : "+f"(c0), "+f"(c1), "+f"(c2), "+f"(c3)
                 : "r"(a0), "r"(a1), "r"(a2), "r"(a3), "r"(b0), "r"(b1));
}

// ------------------------------------------------------------------
// kernel 5: logits via bf16 HMMA, 3-term hi/lo split (effective K = 1536)
// block tile 256x128, 16 warps (4m x 4n), warp tile 64x32, K-tile 32
// SMEM rows padded to 40 bf16 (80 B). Double-buffered cp.async.
// Buffer: A 256*80=20480 B, B 128*80=10240 B -> 30720 B; x2 = 61440 B dynamic.
// ------------------------------------------------------------------
#define LTA_BUF 30720
#define LTA_BOFF 20480

__device__ __forceinline__ void logits_load_tile(
    int kt, int buf, int tid, int mtb, int ntb, uint32_t sbase)
{
    const int pass = kt >> 4;
    const int k0   = (kt & 15) * 32;
    const __nv_bfloat16* pA = (pass == 1) ? g_Alo : g_Ahi;
    const __nv_bfloat16* pB = (pass == 2) ? g_Blo : g_Bhi;
    const uint32_t abase = sbase + buf * LTA_BUF;
    const uint32_t bbase = abase + LTA_BOFF;
    #pragma unroll
    for (int i = 0; i < 3; i++) {
        int slot = tid + i * 512;                 // 0..1535
        if (slot < 1024) {                        // A: 256 rows x 4 segs
            int row = slot >> 2, seg = slot & 3;
            cp_async16(abase + row * 80 + seg * 16,
                       pA + (size_t)(mtb * 256 + row) * HH + k0 + seg * 8);
        } else {                                  // B: 128 rows x 4 segs
            int s2 = slot - 1024;
            int row = s2 >> 2, seg = s2 & 3;
            cp_async16(bbase + row * 80 + seg * 16,
                       pB + (size_t)(ntb * 128 + row) * HH + k0 + seg * 8);
        }
    }
    cp_commit();
}

__global__ void __launch_bounds__(512, 1) k_logits_mma(const float* __restrict__ bv,
                                                       float* __restrict__ out)
{
    extern __shared__ __align__(16) unsigned char lsm[];
    const int tid  = threadIdx.x;
    const int lane = tid & 31;
    const int warp = tid >> 5;
    const int ntb  = blockIdx.x;     // 0..78 (vocab)
    const int mtb  = blockIdx.y;     // 0..15 (rows)

    const int wm = (warp >> 2) * 64;     // 0,64,128,192
    const int wn = (warp & 3) * 32;      // 0,32,64,96

    uint32_t sbase = (uint32_t)__cvta_generic_to_shared(lsm);

    float acc[4][4][4];
    #pragma unroll
    for (int i = 0; i < 4; i++)
        #pragma unroll
        for (int j = 0; j < 4; j++) {
            acc[i][j][0] = 0.f; acc[i][j][1] = 0.f;
            acc[i][j][2] = 0.f; acc[i][j][3] = 0.f;
        }

    // ldmatrix lane address offsets (bytes within a buffer)
    const int amat  = lane >> 3;
    const uint32_t a_lane_off = (uint32_t)((wm + (amat & 1) * 8 + (lane & 7)) * 80
                                           + ((amat >> 1) * 8) * 2);
    const int blane = lane & 15;
    const uint32_t b_lane_off = (uint32_t)(LTA_BOFF + (wn + (blane & 7)) * 80
                                           + ((blane >> 3) * 8) * 2);

    const int NKT = 48;                        // 3 passes * 16 k-tiles
    logits_load_tile(0, 0, tid, mtb, ntb, sbase);

    for (int kt = 0; kt < NKT; kt++) {
        if (kt + 1 < NKT) {
            logits_load_tile(kt + 1, (kt + 1) & 1, tid, mtb, ntb, sbase);
            asm volatile("cp.async.wait_group 1;");
        } else {
            asm volatile("cp.async.wait_group 0;");
        }
        __syncthreads();

        const uint32_t abase = sbase + (kt & 1) * LTA_BUF;
        #pragma unroll
        for (int k16 = 0; k16 < 2; k16++) {
            uint32_t af[4][4];
            uint32_t bf[4][2];
            #pragma unroll
            for (int mt = 0; mt < 4; mt++) {
                uint32_t ad = abase + a_lane_off + mt * (16 * 80) + k16 * 32;
                ldsm_x4(af[mt][0], af[mt][1], af[mt][2], af[mt][3], ad);
            }
            #pragma unroll
            for (int nt = 0; nt < 4; nt++) {
                uint32_t bd = abase + b_lane_off + nt * (8 * 80) + k16 * 32;
                ldsm_x2(bf[nt][0], bf[nt][1], bd);
            }
            #pragma unroll
            for (int mt = 0; mt < 4; mt++)
                #pragma unroll
                for (int nt = 0; nt < 4; nt++)
                    mma16816(acc[mt][nt][0], acc[mt][nt][1],
                             acc[mt][nt][2], acc[mt][nt][3],
                             af[mt][0], af[mt][1], af[mt][2], af[mt][3],
                             bf[nt][0], bf[nt][1]);
        }
        __syncthreads();
    }

    // epilogue: row m = t*32+b  ->  out[b][t][col], add bias
    #pragma unroll
    for (int mt = 0; mt < 4; mt++) {
        #pragma unroll
        for (int nt = 0; nt < 4; nt++) {
            int col = ntb * 128 + wn + nt * 8 + (lane & 3) * 2;
            if (col < VV) {
                float bb0 = __ldg(bv + col);
                float bb1 = __ldg(bv + col + 1);
                int m0 = mtb * 256 + wm + mt * 16 + (lane >> 2);
                int bI = m0 & 31, tI = m0 >> 5;
                float2 v0 = { acc[mt][nt][0] + bb0, acc[mt][nt][1] + bb1 };
                *(float2*)(out + (size_t)bI * TT * VV + (size_t)tI * VV + col) = v0;
                int m1 = m0 + 8;
                bI = m1 & 31; tI = m1 >> 5;
                float2 v1 = { acc[mt][nt][2] + bb0, acc[mt][nt][3] + bb1 };
                *(float2*)(out + (size_t)bI * TT * VV + (size_t)tI * VV + col) = v1;
            }
        }
    }
}

// ------------------------------------------------------------------
extern "C" void kernel_launch(void* const* d_in, const int* in_sizes, int n_in,
                              void* d_out, int out_size)
{
    const float* tv    = (const float*)d_in[0];
    const int*   texts = (const int*)  d_in[1];
    const int*   start = (const int*)  d_in[3];
    const float* emb   = (const float*)d_in[4];
    const float* W_ih  = (const float*)d_in[5];
    const float* b_ih  = (const float*)d_in[6];
    const float* W_hh  = (const float*)d_in[7];
    const float* b_hh  = (const float*)d_in[8];
    const float* Wo_w  = (const float*)d_in[9];
    const float* Wo_b  = (const float*)d_in[10];
    const float* Wh_w  = (const float*)d_in[11];
    const float* Wh_b  = (const float*)d_in[12];
    const float* Wc_w  = (const float*)d_in[13];
    const float* Wc_b  = (const float*)d_in[14];
    const float* Wv_w  = (const float*)d_in[15];
    const float* Wv_b  = (const float*)d_in[16];
    float* out = (float*)d_out;

    const int lstm_smem = (16 * 512 + 64 * 32 * 4 + 16 * 32 + 4 * 32) * 4;
    cudaFuncSetAttribute(k_lstm, cudaFuncAttributeMaxDynamicSharedMemorySize, 69632);
    cudaFuncSetAttribute(k_logits_mma, cudaFuncAttributeMaxDynamicSharedMemorySize, 2 * LTA_BUF);

    k_init<<<6144, 256>>>(tv, Wo_w, Wo_b, Wh_w, Wh_b, Wc_w, Wc_b);
    k_base<<<8192, 256>>>(tv, W_ih, b_ih, b_hh);
    k_G<<<dim3(G4 / GN, (TT * BQ) / GM), 256>>>(emb, texts, start, W_ih);
    k_convB<<<(VPAD * HH) / 256, 256>>>(Wv_w);
    k_lstm<<<128, 256, lstm_smem>>>(W_hh);
    k_convA<<<(TT * BQ * HH) / 256, 256>>>();
    k_logits_mma<<<dim3(VPAD / 128, (TT * BQ) / 256), 512, 2 * LTA_BUF>>>(Wv_b, out);
}

// round 6
// speedup vs baseline: 1.2040x; 1.2040x over previous
#include <cuda_runtime.h>
#include <cuda_bf16.h>
#include <cuda_fp16.h>
#include <cstdint>
#include <math.h>

#define BQ   32
#define TT   128
#define EE   256
#define HH   512
#define ENCC 512
#define VV   10000
#define G4   2048          // 4*H
#define XW   1280          // E + H + ENC
#define VPAD 10112         // 79 * 128

// ------------------------------------------------------------------
// scratch (static device globals; no allocations allowed)
// ------------------------------------------------------------------
__device__ float g_o[BQ * HH];
__device__ float g_c0[BQ * HH];
__device__ float g_base[BQ * G4];
__device__ float g_G[TT * BQ * G4];               // per-step gate input (32 MB)
__device__ float g_hs[(TT + 1) * BQ * HH];        // slot0=h0, slot t+1 = h after step t
__device__ unsigned g_bar_count;
__device__ unsigned g_bar_gen;

// fp16 operands for the tensor-core logits GEMM (single pass)
__device__ __half g_Ah[TT * BQ * HH];             // 4 MB
__device__ __half g_Bh[VPAD * HH];                // 10 MB (zero-padded rows)

// ------------------------------------------------------------------
// kernel 1: o, h0, c0   (warp per output, shuffle reduce)
// ------------------------------------------------------------------
__global__ void k_init(const float* __restrict__ tv,
                       const float* __restrict__ Wo, const float* __restrict__ bo,
                       const float* __restrict__ Wh, const float* __restrict__ bh,
                       const float* __restrict__ Wc, const float* __restrict__ bc)
{
    int warp = (blockIdx.x * blockDim.x + threadIdx.x) >> 5;
    int lane = threadIdx.x & 31;
    if (warp >= 3 * BQ * HH) return;
    int m   = warp / (BQ * HH);
    int rem = warp % (BQ * HH);
    int b = rem / HH, j = rem % HH;
    const float* W    = (m == 0) ? Wo : (m == 1) ? Wh : Wc;
    const float* bias = (m == 0) ? bo : (m == 1) ? bh : bc;
    const float* x = tv + b * ENCC;
    const float* w = W  + j * ENCC;
    float s = 0.f;
    for (int k = lane; k < ENCC; k += 32) s += x[k] * w[k];
    #pragma unroll
    for (int o = 16; o; o >>= 1) s += __shfl_xor_sync(0xffffffffu, s, o);
    if (lane == 0) {
        float v = s + bias[j];
        if (m == 0)      g_o[b * HH + j]  = v;
        else if (m == 1) g_hs[b * HH + j] = v;   // slot 0 = h0
        else             g_c0[b * HH + j] = v;
    }
}

// ------------------------------------------------------------------
// kernel 2: gates_base
// ------------------------------------------------------------------
__global__ void k_base(const float* __restrict__ tv,
                       const float* __restrict__ W_ih,
                       const float* __restrict__ b_ih,
                       const float* __restrict__ b_hh)
{
    int warp = (blockIdx.x * blockDim.x + threadIdx.x) >> 5;
    int lane = threadIdx.x & 31;
    if (warp >= BQ * G4) return;
    int b = warp / G4, n = warp % G4;
    const float* w = W_ih + (size_t)n * XW + EE;
    float s = 0.f;
    for (int k = lane; k < HH + ENCC; k += 32) {
        float x = (k < HH) ? g_o[b * HH + k] : tv[b * ENCC + (k - HH)];
        s += x * w[k];
    }
    #pragma unroll
    for (int o = 16; o; o >>= 1) s += __shfl_xor_sync(0xffffffffu, s, o);
    if (lane == 0) g_base[b * G4 + n] = s + b_ih[n] + b_hh[n];
}

// ------------------------------------------------------------------
// kernel 3: G[t][b][n] = emb[token(t-1)] @ W_ih[:, :E]^T + gates_base
// ------------------------------------------------------------------
#define GM 64
#define GN 64
#define GK 16
__global__ void __launch_bounds__(256) k_G(const float* __restrict__ emb,
                                           const int*   __restrict__ texts,
                                           const int*   __restrict__ startp,
                                           const float* __restrict__ W_ih)
{
    __shared__ float As[GK][GM + 4];
    __shared__ float Bs[GK][GN + 4];
    __shared__ int   rowoff[GM];
    int tid = threadIdx.x;
    int nt = blockIdx.x, mt = blockIdx.y;

    if (tid < GM) {
        int r = mt * GM + tid;
        int t = r >> 5, b = r & 31;
        int tok = (t == 0) ? startp[0] : texts[b * TT + t - 1];
        rowoff[tid] = tok * EE;
    }
    __syncthreads();

    int tm = tid >> 4, tn = tid & 15;
    int lrow = tid >> 2;
    int lk   = (tid & 3) * 4;
    float acc[4][4] = {};

    for (int k0 = 0; k0 < EE; k0 += GK) {
        float4 av = *(const float4*)(emb + rowoff[lrow] + k0 + lk);
        float4 bv = *(const float4*)(W_ih + (size_t)(nt * GN + lrow) * XW + k0 + lk);
        __syncthreads();
        As[lk + 0][lrow] = av.x; As[lk + 1][lrow] = av.y;
        As[lk + 2][lrow] = av.z; As[lk + 3][lrow] = av.w;
        Bs[lk + 0][lrow] = bv.x; Bs[lk + 1][lrow] = bv.y;
        Bs[lk + 2][lrow] = bv.z; Bs[lk + 3][lrow] = bv.w;
        __syncthreads();
        #pragma unroll
        for (int kk = 0; kk < GK; kk++) {
            float4 a4 = *(const float4*)&As[kk][tm * 4];
            float4 b4 = *(const float4*)&Bs[kk][tn * 4];
            float ar[4] = {a4.x, a4.y, a4.z, a4.w};
            float br[4] = {b4.x, b4.y, b4.z, b4.w};
            #pragma unroll
            for (int i = 0; i < 4; i++)
                #pragma unroll
                for (int j = 0; j < 4; j++)
                    acc[i][j] = fmaf(ar[i], br[j], acc[i][j]);
        }
    }
    #pragma unroll
    for (int i = 0; i < 4; i++) {
        int r = mt * GM + tm * 4 + i;
        int ncol = nt * GN + tn * 4;
        float4 bs = *(const float4*)&g_base[(r & 31) * G4 + ncol];
        float4 v;
        v.x = acc[i][0] + bs.x; v.y = acc[i][1] + bs.y;
        v.z = acc[i][2] + bs.z; v.w = acc[i][3] + bs.w;
        *(float4*)&g_G[(size_t)r * G4 + ncol] = v;
    }
}

// ------------------------------------------------------------------
// kernel 4: sequential LSTM (persistent, 128 CTAs, grid barrier per step)
// ------------------------------------------------------------------
__global__ void __launch_bounds__(256, 1) k_lstm(const float* __restrict__ W_hh)
{
    extern __shared__ float smem[];
    float*  sW    = smem;
    float4* sW4   = (float4*)sW;
    float*  sH    = smem + 16 * 512;
    float4* sH4   = (float4*)sH;
    float*  sGate = sH + 64 * 32 * 4;
    float*  sC    = sGate + 16 * 32;
    __shared__ unsigned sGen;

    int tid = threadIdx.x;
    int p   = blockIdx.x;
    int b   = tid & 31;
    int rr  = tid >> 5;
    int lr0 = rr, lr1 = rr + 8;
    int n0 = (lr0 >> 2) * HH + p * 4 + (lr0 & 3);
    int n1 = (lr1 >> 2) * HH + p * 4 + (lr1 & 3);

    for (int idx = tid; idx < 16 * 128; idx += 256) {
        int lr = idx >> 7, k4 = idx & 127;
        int n  = (lr >> 2) * HH + p * 4 + (lr & 3);
        sW4[lr * 128 + k4] = *(const float4*)(W_hh + (size_t)n * HH + k4 * 4);
    }
    if (tid < 128) {
        int q = tid >> 5, b2 = tid & 31;
        sC[q * 32 + b2] = g_c0[b2 * HH + p * 4 + q];
    }
    if (tid == 0) sGen = g_bar_gen;
    __syncthreads();
    unsigned base_gen = sGen;

    for (int t = 0; t < TT; t++) {
        const float* hprev = g_hs + (size_t)t * (BQ * HH);
        float4 accA = {0, 0, 0, 0}, accB = {0, 0, 0, 0};
        #pragma unroll
        for (int half = 0; half < 2; half++) {
            for (int idx = tid; idx < 64 * 32; idx += 256) {
                int k4 = idx >> 5, bb = idx & 31;
                sH4[idx] = __ldcg((const float4*)(hprev + bb * HH + half * 256 + k4 * 4));
            }
            __syncthreads();
            const float4* wA = sW4 + lr0 * 128 + half * 64;
            const float4* wB = sW4 + lr1 * 128 + half * 64;
            #pragma unroll 4
            for (int k4 = 0; k4 < 64; k4++) {
                float4 h4 = sH4[k4 * 32 + b];
                float4 a  = wA[k4];
                float4 c  = wB[k4];
                accA.x = fmaf(h4.x, a.x, accA.x);
                accA.y = fmaf(h4.y, a.y, accA.y);
                accA.z = fmaf(h4.z, a.z, accA.z);
                accA.w = fmaf(h4.w, a.w, accA.w);
                accB.x = fmaf(h4.x, c.x, accB.x);
                accB.y = fmaf(h4.y, c.y, accB.y);
                accB.z = fmaf(h4.z, c.z, accB.z);
                accB.w = fmaf(h4.w, c.w, accB.w);
            }
            __syncthreads();
        }
        float gA = (accA.x + accA.y) + (accA.z + accA.w)
                 + g_G[(size_t)(t * BQ + b) * G4 + n0];
        float gB = (accB.x + accB.y) + (accB.z + accB.w)
                 + g_G[(size_t)(t * BQ + b) * G4 + n1];
        sGate[lr0 * 32 + b] = gA;
        sGate[lr1 * 32 + b] = gB;
        __syncthreads();
        if (tid < 128) {
            int q = tid >> 5, b2 = tid & 31;
            float ig = sGate[(q     ) * 32 + b2];
            float fg = sGate[(4  + q) * 32 + b2];
            float gg = sGate[(8  + q) * 32 + b2];
            float og = sGate[(12 + q) * 32 + b2];
            float iS = 1.f / (1.f + expf(-ig));
            float fS = 1.f / (1.f + expf(-fg));
            float gT = tanhf(gg);
            float oS = 1.f / (1.f + expf(-og));
            float c  = fS * sC[q * 32 + b2] + iS * gT;
            sC[q * 32 + b2] = c;
            float h = oS * tanhf(c);
            g_hs[(size_t)(t + 1) * (BQ * HH) + b2 * HH + p * 4 + q] = h;
        }
        __threadfence();
        __syncthreads();
        if (tid == 0) {
            unsigned target = base_gen + (unsigned)(t + 1);
            unsigned arr = atomicAdd(&g_bar_count, 1u);
            if (arr == 127u) {
                g_bar_count = 0u;
                __threadfence();
                atomicExch(&g_bar_gen, target);
            } else {
                volatile unsigned* vg = &g_bar_gen;
                while (*vg < target) { }
            }
            __threadfence();
        }
        __syncthreads();
    }
}

// ------------------------------------------------------------------
// conversion kernels: fp32 -> fp16
// ------------------------------------------------------------------
__global__ void k_convA()
{
    int idx = blockIdx.x * 256 + threadIdx.x;          // TT*BQ*HH = 2097152
    g_Ah[idx] = __float2half_rn(g_hs[BQ * HH + idx]);
}

__global__ void k_convB(const float* __restrict__ Wv)
{
    size_t idx = (size_t)blockIdx.x * 256 + threadIdx.x;   // VPAD*HH
    int n = (int)(idx >> 9);
    float x = (n < VV) ? Wv[idx] : 0.f;
    g_Bh[idx] = __float2half_rn(x);
}

// ------------------------------------------------------------------
// mma / ldmatrix / cp.async helpers
// ------------------------------------------------------------------
__device__ __forceinline__ void cp_async16(uint32_t dst, const void* src)
{
    asm volatile("cp.async.cg.shared.global [%0], [%1], 16;" :: "r"(dst), "l"(src));
}
__device__ __forceinline__ void cp_commit()
{
    asm volatile("cp.async.commit_group;");
}
__device__ __forceinline__ void ldsm_x4(uint32_t& r0, uint32_t& r1,
                                        uint32_t& r2, uint32_t& r3, uint32_t addr)
{
    asm volatile("ldmatrix.sync.aligned.m8n8.x4.shared.b16 {%0,%1,%2,%3}, [%4];"
                 : "=r"(r0), "=r"(r1), "=r"(r2), "=r"(r3) : "r"(addr));
}
__device__ __forceinline__ void ldsm_x2(uint32_t& r0, uint32_t& r1, uint32_t addr)
{
    asm volatile("ldmatrix.sync.aligned.m8n8.x2.shared.b16 {%0,%1}, [%2];"
                 : "=r"(r0), "=r"(r1) : "r"(addr));
}
__device__ __forceinline__ void mma16816(float& c0, float& c1, float& c2, float& c3,
                                         uint32_t a0, uint32_t a1, uint32_t a2, uint32_t a3,
                                         uint32_t b0, uint32_t b1)
{
    asm volatile("mma.sync.aligned.m16n8k16.row.col.f32.f16.f16.f32 "
                 "{%0,%1,%2,%3}, {%4,%5,%6,%7}, {%8,%9}, {%0,%1,%2,%3};"
                 : "+f"(c0), "+f"(c1), "+f"(c2), "+f"(c3)
                 : "r"(a0), "r"(a1), "r"(a2), "r"(a3), "r"(b0), "r"(b1));
}

// ------------------------------------------------------------------
// kernel 5: logits via fp16 HMMA, single pass (K = 512)
// block tile 128x128, 8 warps (2m x 4n), warp tile 64x32, K-tile 32
// SMEM rows padded to 40 halves (80 B) for conflict-free ldmatrix
// ------------------------------------------------------------------
#define MMA_SMEM_BUF 20480           // A(10240) + B(10240) per buffer

__device__ __forceinline__ void logits_load_tile(
    int kt, int buf, int tid, int mtb, int ntb, uint32_t sbase)
{
    const int k0 = kt * 32;
    const uint32_t abase = sbase + buf * MMA_SMEM_BUF;
    const uint32_t bbase = abase + 10240;
    #pragma unroll
    for (int i = 0; i < 2; i++) {
        int ch  = tid + i * 256;          // 0..511
        int row = ch >> 2, kc = ch & 3;
        cp_async16(abase + row * 80 + kc * 16,
                   g_Ah + (size_t)(mtb * 128 + row) * HH + k0 + kc * 8);
        cp_async16(bbase + row * 80 + kc * 16,
                   g_Bh + (size_t)(ntb * 128 + row) * HH + k0 + kc * 8);
    }
    cp_commit();
}

__global__ void __launch_bounds__(256) k_logits_mma(const float* __restrict__ bv,
                                                    float* __restrict__ out)
{
    __shared__ __align__(16) unsigned char smem[2 * MMA_SMEM_BUF];
    const int tid  = threadIdx.x;
    const int lane = tid & 31;
    const int warp = tid >> 5;
    const int ntb  = blockIdx.x;     // 0..78
    const int mtb  = blockIdx.y;     // 0..31

    const int wm = (warp >> 2) * 64;
    const int wn = (warp & 3) * 32;

    uint32_t sbase = (uint32_t)__cvta_generic_to_shared(smem);

    float acc[4][4][4];
    #pragma unroll
    for (int i = 0; i < 4; i++)
        #pragma unroll
        for (int j = 0; j < 4; j++) {
            acc[i][j][0] = 0.f; acc[i][j][1] = 0.f;
            acc[i][j][2] = 0.f; acc[i][j][3] = 0.f;
        }

    // ldmatrix lane address offsets (bytes within a buffer)
    const int amat  = lane >> 3;
    const uint32_t a_lane_off = (uint32_t)((wm + (amat & 1) * 8 + (lane & 7)) * 80
                                           + ((amat >> 1) * 8) * 2);
    const int blane = lane & 15;
    const uint32_t b_lane_off = (uint32_t)(10240 + (wn + (blane & 7)) * 80
                                           + ((blane >> 3) * 8) * 2);

    const int NKT = 16;                        // 512 / 32
    logits_load_tile(0, 0, tid, mtb, ntb, sbase);

    for (int kt = 0; kt < NKT; kt++) {
        if (kt + 1 < NKT) {
            logits_load_tile(kt + 1, (kt + 1) & 1, tid, mtb, ntb, sbase);
            asm volatile("cp.async.wait_group 1;");
        } else {
            asm volatile("cp.async.wait_group 0;");
        }
        __syncthreads();

        const uint32_t abase = sbase + (kt & 1) * MMA_SMEM_BUF;
        #pragma unroll
        for (int k16 = 0; k16 < 2; k16++) {
            uint32_t af[4][4];
            uint32_t bf[4][2];
            #pragma unroll
            for (int mt = 0; mt < 4; mt++) {
                uint32_t ad = abase + a_lane_off + mt * (16 * 80) + k16 * 32;
                ldsm_x4(af[mt][0], af[mt][1], af[mt][2], af[mt][3], ad);
            }
            #pragma unroll
            for (int nt = 0; nt < 4; nt++) {
                uint32_t bd = abase + b_lane_off + nt * (8 * 80) + k16 * 32;
                ldsm_x2(bf[nt][0], bf[nt][1], bd);
            }
            #pragma unroll
            for (int mt = 0; mt < 4; mt++)
                #pragma unroll
                for (int nt = 0; nt < 4; nt++)
                    mma16816(acc[mt][nt][0], acc[mt][nt][1],
                             acc[mt][nt][2], acc[mt][nt][3],
                             af[mt][0], af[mt][1], af[mt][2], af[mt][3],
                             bf[nt][0], bf[nt][1]);
        }
        __syncthreads();
    }

    // epilogue: row m = t*32+b  ->  out[b][t][col], add bias
    #pragma unroll
    for (int mt = 0; mt < 4; mt++) {
        #pragma unroll
        for (int nt = 0; nt < 4; nt++) {
            int col = ntb * 128 + wn + nt * 8 + (lane & 3) * 2;
            if (col < VV) {
                float bb0 = __ldg(bv + col);
                float bb1 = __ldg(bv + col + 1);
                int m0 = mtb * 128 + wm + mt * 16 + (lane >> 2);
                int bI = m0 & 31, tI = m0 >> 5;
                float2 v0 = { acc[mt][nt][0] + bb0, acc[mt][nt][1] + bb1 };
                *(float2*)(out + (size_t)bI * TT * VV + (size_t)tI * VV + col) = v0;
                int m1 = m0 + 8;
                bI = m1 & 31; tI = m1 >> 5;
                float2 v1 = { acc[mt][nt][2] + bb0, acc[mt][nt][3] + bb1 };
                *(float2*)(out + (size_t)bI * TT * VV + (size_t)tI * VV + col) = v1;
            }
        }
    }
}

// ------------------------------------------------------------------
extern "C" void kernel_launch(void* const* d_in, const int* in_sizes, int n_in,
                              void* d_out, int out_size)
{
    const float* tv    = (const float*)d_in[0];
    const int*   texts = (const int*)  d_in[1];
    const int*   start = (const int*)  d_in[3];
    const float* emb   = (const float*)d_in[4];
    const float* W_ih  = (const float*)d_in[5];
    const float* b_ih  = (const float*)d_in[6];
    const float* W_hh  = (const float*)d_in[7];
    const float* b_hh  = (const float*)d_in[8];
    const float* Wo_w  = (const float*)d_in[9];
    const float* Wo_b  = (const float*)d_in[10];
    const float* Wh_w  = (const float*)d_in[11];
    const float* Wh_b  = (const float*)d_in[12];
    const float* Wc_w  = (const float*)d_in[13];
    const float* Wc_b  = (const float*)d_in[14];
    const float* Wv_w  = (const float*)d_in[15];
    const float* Wv_b  = (const float*)d_in[16];
    float* out = (float*)d_out;

    const int lstm_smem = (16 * 512 + 64 * 32 * 4 + 16 * 32 + 4 * 32) * 4;
    cudaFuncSetAttribute(k_lstm, cudaFuncAttributeMaxDynamicSharedMemorySize, 69632);

    k_init<<<6144, 256>>>(tv, Wo_w, Wo_b, Wh_w, Wh_b, Wc_w, Wc_b);
    k_base<<<8192, 256>>>(tv, W_ih, b_ih, b_hh);
    k_G<<<dim3(G4 / GN, (TT * BQ) / GM), 256>>>(emb, texts, start, W_ih);
    k_convB<<<(VPAD * HH) / 256, 256>>>(Wv_w);
    k_lstm<<<128, 256, lstm_smem>>>(W_hh);
    k_convA<<<(TT * BQ * HH) / 256, 256>>>();
    k_logits_mma<<<dim3(VPAD / 128, (TT * BQ) / 128), 256>>>(Wv_b, out);
}

// round 7
// speedup vs baseline: 1.2569x; 1.0439x over previous
#include <cuda_runtime.h>
#include <cuda_bf16.h>
#include <cuda_fp16.h>
#include <cstdint>
#include <math.h>

#define BQ   32
#define TT   128
#define EE   256
#define HH   512
#define ENCC 512
#define VV   10000
#define G4   2048          // 4*H
#define XW   1280          // E + H + ENC
#define VPAD 10112         // 79 * 128

// ------------------------------------------------------------------
// scratch (static device globals; no allocations allowed)
// ------------------------------------------------------------------
__device__ float g_o[BQ * HH];
__device__ float g_c0[BQ * HH];
__device__ float g_base[BQ * G4];
__device__ float g_G[TT * BQ * G4];               // per-step gate input (32 MB)
__device__ float g_hs[(TT + 1) * BQ * HH];        // slot0=h0, slot t+1 = h after step t
__device__ unsigned g_bar_count;
__device__ unsigned g_bar_gen;

// fp16 operands
__device__ __half g_Ah[TT * BQ * HH];             // logits A (hs) fp16, 4 MB
__device__ __half g_Bh[VPAD * HH];                // logits B (Wv) fp16, 10 MB
__device__ __half g_E[TT * BQ * EE];              // gathered prev-token embeddings, 2 MB
__device__ __half g_Wih16[G4 * EE];               // W_ih[:, :E] fp16, 1 MB

// ------------------------------------------------------------------
// kernel 1: o, h0, c0   (warp per output, shuffle reduce)
// ------------------------------------------------------------------
__global__ void k_init(const float* __restrict__ tv,
                       const float* __restrict__ Wo, const float* __restrict__ bo,
                       const float* __restrict__ Wh, const float* __restrict__ bh,
                       const float* __restrict__ Wc, const float* __restrict__ bc)
{
    int warp = (blockIdx.x * blockDim.x + threadIdx.x) >> 5;
    int lane = threadIdx.x & 31;
    if (warp >= 3 * BQ * HH) return;
    int m   = warp / (BQ * HH);
    int rem = warp % (BQ * HH);
    int b = rem / HH, j = rem % HH;
    const float* W    = (m == 0) ? Wo : (m == 1) ? Wh : Wc;
    const float* bias = (m == 0) ? bo : (m == 1) ? bh : bc;
    const float* x = tv + b * ENCC;
    const float* w = W  + j * ENCC;
    float s = 0.f;
    for (int k = lane; k < ENCC; k += 32) s += x[k] * w[k];
    #pragma unroll
    for (int o = 16; o; o >>= 1) s += __shfl_xor_sync(0xffffffffu, s, o);
    if (lane == 0) {
        float v = s + bias[j];
        if (m == 0)      g_o[b * HH + j]  = v;
        else if (m == 1) g_hs[b * HH + j] = v;   // slot 0 = h0
        else             g_c0[b * HH + j] = v;
    }
}

// ------------------------------------------------------------------
// kernel 2: gates_base
// ------------------------------------------------------------------
__global__ void k_base(const float* __restrict__ tv,
                       const float* __restrict__ W_ih,
                       const float* __restrict__ b_ih,
                       const float* __restrict__ b_hh)
{
    int warp = (blockIdx.x * blockDim.x + threadIdx.x) >> 5;
    int lane = threadIdx.x & 31;
    if (warp >= BQ * G4) return;
    int b = warp / G4, n = warp % G4;
    const float* w = W_ih + (size_t)n * XW + EE;
    float s = 0.f;
    for (int k = lane; k < HH + ENCC; k += 32) {
        float x = (k < HH) ? g_o[b * HH + k] : tv[b * ENCC + (k - HH)];
        s += x * w[k];
    }
    #pragma unroll
    for (int o = 16; o; o >>= 1) s += __shfl_xor_sync(0xffffffffu, s, o);
    if (lane == 0) g_base[b * G4 + n] = s + b_ih[n] + b_hh[n];
}

// ------------------------------------------------------------------
// kernel 3a: gather prev-token embeddings as dense fp16 A [4096 x 256]
// row r = t*32+b : token = (t==0) ? start : texts[b][t-1]
// ------------------------------------------------------------------
__global__ void k_gather(const float* __restrict__ emb,
                         const int*   __restrict__ texts,
                         const int*   __restrict__ startp)
{
    int r = blockIdx.x;                 // 0..4095
    int t = r >> 5, b = r & 31;
    int tok = (t == 0) ? startp[0] : texts[b * TT + t - 1];
    const float* src = emb + (size_t)tok * EE;
    int k = threadIdx.x * 4;            // 64 threads x 4
    float4 v = *(const float4*)(src + k);
    __half2 h0 = __floats2half2_rn(v.x, v.y);
    __half2 h1 = __floats2half2_rn(v.z, v.w);
    *(__half2*)(g_E + (size_t)r * EE + k)     = h0;
    *(__half2*)(g_E + (size_t)r * EE + k + 2) = h1;
}

// ------------------------------------------------------------------
// kernel 3b: W_ih[:, :E] -> fp16 [2048 x 256]
// ------------------------------------------------------------------
__global__ void k_convW(const float* __restrict__ W_ih)
{
    int e = (blockIdx.x * 256 + threadIdx.x) * 4;   // 0..524284
    int n = e >> 8, k = e & 255;
    float4 v = *(const float4*)(W_ih + (size_t)n * XW + k);
    __half2 h0 = __floats2half2_rn(v.x, v.y);
    __half2 h1 = __floats2half2_rn(v.z, v.w);
    *(__half2*)(g_Wih16 + (size_t)n * EE + k)     = h0;
    *(__half2*)(g_Wih16 + (size_t)n * EE + k + 2) = h1;
}

// ------------------------------------------------------------------
// kernel 4: sequential LSTM (persistent, 128 CTAs, grid barrier per step)
// ------------------------------------------------------------------
__global__ void __launch_bounds__(256, 1) k_lstm(const float* __restrict__ W_hh)
{
    extern __shared__ float smem[];
    float*  sW    = smem;
    float4* sW4   = (float4*)sW;
    float*  sH    = smem + 16 * 512;
    float4* sH4   = (float4*)sH;
    float*  sGate = sH + 64 * 32 * 4;
    float*  sC    = sGate + 16 * 32;
    __shared__ unsigned sGen;

    int tid = threadIdx.x;
    int p   = blockIdx.x;
    int b   = tid & 31;
    int rr  = tid >> 5;
    int lr0 = rr, lr1 = rr + 8;
    int n0 = (lr0 >> 2) * HH + p * 4 + (lr0 & 3);
    int n1 = (lr1 >> 2) * HH + p * 4 + (lr1 & 3);

    for (int idx = tid; idx < 16 * 128; idx += 256) {
        int lr = idx >> 7, k4 = idx & 127;
        int n  = (lr >> 2) * HH + p * 4 + (lr & 3);
        sW4[lr * 128 + k4] = *(const float4*)(W_hh + (size_t)n * HH + k4 * 4);
    }
    if (tid < 128) {
        int q = tid >> 5, b2 = tid & 31;
        sC[q * 32 + b2] = g_c0[b2 * HH + p * 4 + q];
    }
    if (tid == 0) sGen = g_bar_gen;
    __syncthreads();
    unsigned base_gen = sGen;

    for (int t = 0; t < TT; t++) {
        const float* hprev = g_hs + (size_t)t * (BQ * HH);
        float4 accA = {0, 0, 0, 0}, accB = {0, 0, 0, 0};
        #pragma unroll
        for (int half = 0; half < 2; half++) {
            for (int idx = tid; idx < 64 * 32; idx += 256) {
                int k4 = idx >> 5, bb = idx & 31;
                sH4[idx] = __ldcg((const float4*)(hprev + bb * HH + half * 256 + k4 * 4));
            }
            __syncthreads();
            const float4* wA = sW4 + lr0 * 128 + half * 64;
            const float4* wB = sW4 + lr1 * 128 + half * 64;
            #pragma unroll 4
            for (int k4 = 0; k4 < 64; k4++) {
                float4 h4 = sH4[k4 * 32 + b];
                float4 a  = wA[k4];
                float4 c  = wB[k4];
                accA.x = fmaf(h4.x, a.x, accA.x);
                accA.y = fmaf(h4.y, a.y, accA.y);
                accA.z = fmaf(h4.z, a.z, accA.z);
                accA.w = fmaf(h4.w, a.w, accA.w);
                accB.x = fmaf(h4.x, c.x, accB.x);
                accB.y = fmaf(h4.y, c.y, accB.y);
                accB.z = fmaf(h4.z, c.z, accB.z);
                accB.w = fmaf(h4.w, c.w, accB.w);
            }
            __syncthreads();
        }
        float gA = (accA.x + accA.y) + (accA.z + accA.w)
                 + g_G[(size_t)(t * BQ + b) * G4 + n0];
        float gB = (accB.x + accB.y) + (accB.z + accB.w)
                 + g_G[(size_t)(t * BQ + b) * G4 + n1];
        sGate[lr0 * 32 + b] = gA;
        sGate[lr1 * 32 + b] = gB;
        __syncthreads();
        if (tid < 128) {
            int q = tid >> 5, b2 = tid & 31;
            float ig = sGate[(q     ) * 32 + b2];
            float fg = sGate[(4  + q) * 32 + b2];
            float gg = sGate[(8  + q) * 32 + b2];
            float og = sGate[(12 + q) * 32 + b2];
            float iS = 1.f / (1.f + expf(-ig));
            float fS = 1.f / (1.f + expf(-fg));
            float gT = tanhf(gg);
            float oS = 1.f / (1.f + expf(-og));
            float c  = fS * sC[q * 32 + b2] + iS * gT;
            sC[q * 32 + b2] = c;
            float h = oS * tanhf(c);
            g_hs[(size_t)(t + 1) * (BQ * HH) + b2 * HH + p * 4 + q] = h;
        }
        __threadfence();
        __syncthreads();
        if (tid == 0) {
            unsigned target = base_gen + (unsigned)(t + 1);
            unsigned arr = atomicAdd(&g_bar_count, 1u);
            if (arr == 127u) {
                g_bar_count = 0u;
                __threadfence();
                atomicExch(&g_bar_gen, target);
            } else {
                volatile unsigned* vg = &g_bar_gen;
                while (*vg < target) { }
            }
            __threadfence();
        }
        __syncthreads();
    }
}

// ------------------------------------------------------------------
// conversion kernels: fp32 -> fp16
// ------------------------------------------------------------------
__global__ void k_convA()
{
    int idx = blockIdx.x * 256 + threadIdx.x;          // TT*BQ*HH = 2097152
    g_Ah[idx] = __float2half_rn(g_hs[BQ * HH + idx]);
}

__global__ void k_convB(const float* __restrict__ Wv)
{
    size_t idx = (size_t)blockIdx.x * 256 + threadIdx.x;   // VPAD*HH
    int n = (int)(idx >> 9);
    float x = (n < VV) ? Wv[idx] : 0.f;
    g_Bh[idx] = __float2half_rn(x);
}

// ------------------------------------------------------------------
// mma / ldmatrix / cp.async helpers
// ------------------------------------------------------------------
__device__ __forceinline__ void cp_async16(uint32_t dst, const void* src)
{
    asm volatile("cp.async.cg.shared.global [%0], [%1], 16;" :: "r"(dst), "l"(src));
}
__device__ __forceinline__ void cp_commit()
{
    asm volatile("cp.async.commit_group;");
}
__device__ __forceinline__ void ldsm_x4(uint32_t& r0, uint32_t& r1,
                                        uint32_t& r2, uint32_t& r3, uint32_t addr)
{
    asm volatile("ldmatrix.sync.aligned.m8n8.x4.shared.b16 {%0,%1,%2,%3}, [%4];"
                 : "=r"(r0), "=r"(r1), "=r"(r2), "=r"(r3) : "r"(addr));
}
__device__ __forceinline__ void ldsm_x2(uint32_t& r0, uint32_t& r1, uint32_t addr)
{
    asm volatile("ldmatrix.sync.aligned.m8n8.x2.shared.b16 {%0,%1}, [%2];"
                 : "=r"(r0), "=r"(r1) : "r"(addr));
}
__device__ __forceinline__ void mma16816(float& c0, float& c1, float& c2, float& c3,
                                         uint32_t a0, uint32_t a1, uint32_t a2, uint32_t a3,
                                         uint32_t b0, uint32_t b1)
{
    asm volatile("mma.sync.aligned.m16n8k16.row.col.f32.f16.f16.f32 "
                 "{%0,%1,%2,%3}, {%4,%5,%6,%7}, {%8,%9}, {%0,%1,%2,%3};"
                 : "+f"(c0), "+f"(c1), "+f"(c2), "+f"(c3)
                 : "r"(a0), "r"(a1), "r"(a2), "r"(a3), "r"(b0), "r"(b1));
}

#define MMA_SMEM_BUF 20480           // A(10240) + B(10240) per buffer

// ------------------------------------------------------------------
// kernel 5: G = E @ Wih^T + base  (fp16 HMMA, K=256)
// block tile 128x128, 8 warps (2m x 4n), warp tile 64x32
// ------------------------------------------------------------------
__device__ __forceinline__ void g_load_tile(
    int kt, int buf, int tid, int mtb, int ntb, uint32_t sbase)
{
    const int k0 = kt * 32;
    const uint32_t abase = sbase + buf * MMA_SMEM_BUF;
    const uint32_t bbase = abase + 10240;
    #pragma unroll
    for (int i = 0; i < 2; i++) {
        int ch  = tid + i * 256;
        int row = ch >> 2, kc = ch & 3;
        cp_async16(abase + row * 80 + kc * 16,
                   g_E + (size_t)(mtb * 128 + row) * EE + k0 + kc * 8);
        cp_async16(bbase + row * 80 + kc * 16,
                   g_Wih16 + (size_t)(ntb * 128 + row) * EE + k0 + kc * 8);
    }
    cp_commit();
}

__global__ void __launch_bounds__(256) k_G_mma()
{
    __shared__ __align__(16) unsigned char smem[2 * MMA_SMEM_BUF];
    const int tid  = threadIdx.x;
    const int lane = tid & 31;
    const int warp = tid >> 5;
    const int ntb  = blockIdx.x;     // 0..15
    const int mtb  = blockIdx.y;     // 0..31

    const int wm = (warp >> 2) * 64;
    const int wn = (warp & 3) * 32;

    uint32_t sbase = (uint32_t)__cvta_generic_to_shared(smem);

    float acc[4][4][4];
    #pragma unroll
    for (int i = 0; i < 4; i++)
        #pragma unroll
        for (int j = 0; j < 4; j++) {
            acc[i][j][0] = 0.f; acc[i][j][1] = 0.f;
            acc[i][j][2] = 0.f; acc[i][j][3] = 0.f;
        }

    const int amat  = lane >> 3;
    const uint32_t a_lane_off = (uint32_t)((wm + (amat & 1) * 8 + (lane & 7)) * 80
                                           + ((amat >> 1) * 8) * 2);
    const int blane = lane & 15;
    const uint32_t b_lane_off = (uint32_t)(10240 + (wn + (blane & 7)) * 80
                                           + ((blane >> 3) * 8) * 2);

    const int NKT = 8;                         // 256 / 32
    g_load_tile(0, 0, tid, mtb, ntb, sbase);

    for (int kt = 0; kt < NKT; kt++) {
        if (kt + 1 < NKT) {
            g_load_tile(kt + 1, (kt + 1) & 1, tid, mtb, ntb, sbase);
            asm volatile("cp.async.wait_group 1;");
        } else {
            asm volatile("cp.async.wait_group 0;");
        }
        __syncthreads();

        const uint32_t abase = sbase + (kt & 1) * MMA_SMEM_BUF;
        #pragma unroll
        for (int k16 = 0; k16 < 2; k16++) {
            uint32_t af[4][4];
            uint32_t bf[4][2];
            #pragma unroll
            for (int mt = 0; mt < 4; mt++) {
                uint32_t ad = abase + a_lane_off + mt * (16 * 80) + k16 * 32;
                ldsm_x4(af[mt][0], af[mt][1], af[mt][2], af[mt][3], ad);
            }
            #pragma unroll
            for (int nt = 0; nt < 4; nt++) {
                uint32_t bd = abase + b_lane_off + nt * (8 * 80) + k16 * 32;
                ldsm_x2(bf[nt][0], bf[nt][1], bd);
            }
            #pragma unroll
            for (int mt = 0; mt < 4; mt++)
                #pragma unroll
                for (int nt = 0; nt < 4; nt++)
                    mma16816(acc[mt][nt][0], acc[mt][nt][1],
                             acc[mt][nt][2], acc[mt][nt][3],
                             af[mt][0], af[mt][1], af[mt][2], af[mt][3],
                             bf[nt][0], bf[nt][1]);
        }
        __syncthreads();
    }

    // epilogue: G[m][col] = acc + base[(m&31)][col]
    #pragma unroll
    for (int mt = 0; mt < 4; mt++) {
        #pragma unroll
        for (int nt = 0; nt < 4; nt++) {
            int col = ntb * 128 + wn + nt * 8 + (lane & 3) * 2;
            int m0 = mtb * 128 + wm + mt * 16 + (lane >> 2);
            float2 bs0 = *(const float2*)&g_base[(m0 & 31) * G4 + col];
            float2 v0 = { acc[mt][nt][0] + bs0.x, acc[mt][nt][1] + bs0.y };
            *(float2*)&g_G[(size_t)m0 * G4 + col] = v0;
            int m1 = m0 + 8;
            float2 bs1 = *(const float2*)&g_base[(m1 & 31) * G4 + col];
            float2 v1 = { acc[mt][nt][2] + bs1.x, acc[mt][nt][3] + bs1.y };
            *(float2*)&g_G[(size_t)m1 * G4 + col] = v1;
        }
    }
}

// ------------------------------------------------------------------
// kernel 6: logits via fp16 HMMA, single pass (K = 512)
// ------------------------------------------------------------------
__device__ __forceinline__ void logits_load_tile(
    int kt, int buf, int tid, int mtb, int ntb, uint32_t sbase)
{
    const int k0 = kt * 32;
    const uint32_t abase = sbase + buf * MMA_SMEM_BUF;
    const uint32_t bbase = abase + 10240;
    #pragma unroll
    for (int i = 0; i < 2; i++) {
        int ch  = tid + i * 256;
        int row = ch >> 2, kc = ch & 3;
        cp_async16(abase + row * 80 + kc * 16,
                   g_Ah + (size_t)(mtb * 128 + row) * HH + k0 + kc * 8);
        cp_async16(bbase + row * 80 + kc * 16,
                   g_Bh + (size_t)(ntb * 128 + row) * HH + k0 + kc * 8);
    }
    cp_commit();
}

__global__ void __launch_bounds__(256) k_logits_mma(const float* __restrict__ bv,
                                                    float* __restrict__ out)
{
    __shared__ __align__(16) unsigned char smem[2 * MMA_SMEM_BUF];
    const int tid  = threadIdx.x;
    const int lane = tid & 31;
    const int warp = tid >> 5;
    const int ntb  = blockIdx.x;     // 0..78
    const int mtb  = blockIdx.y;     // 0..31

    const int wm = (warp >> 2) * 64;
    const int wn = (warp & 3) * 32;

    uint32_t sbase = (uint32_t)__cvta_generic_to_shared(smem);

    float acc[4][4][4];
    #pragma unroll
    for (int i = 0; i < 4; i++)
        #pragma unroll
        for (int j = 0; j < 4; j++) {
            acc[i][j][0] = 0.f; acc[i][j][1] = 0.f;
            acc[i][j][2] = 0.f; acc[i][j][3] = 0.f;
        }

    const int amat  = lane >> 3;
    const uint32_t a_lane_off = (uint32_t)((wm + (amat & 1) * 8 + (lane & 7)) * 80
                                           + ((amat >> 1) * 8) * 2);
    const int blane = lane & 15;
    const uint32_t b_lane_off = (uint32_t)(10240 + (wn + (blane & 7)) * 80
                                           + ((blane >> 3) * 8) * 2);

    const int NKT = 16;                        // 512 / 32
    logits_load_tile(0, 0, tid, mtb, ntb, sbase);

    for (int kt = 0; kt < NKT; kt++) {
        if (kt + 1 < NKT) {
            logits_load_tile(kt + 1, (kt + 1) & 1, tid, mtb, ntb, sbase);
            asm volatile("cp.async.wait_group 1;");
        } else {
            asm volatile("cp.async.wait_group 0;");
        }
        __syncthreads();

        const uint32_t abase = sbase + (kt & 1) * MMA_SMEM_BUF;
        #pragma unroll
        for (int k16 = 0; k16 < 2; k16++) {
            uint32_t af[4][4];
            uint32_t bf[4][2];
            #pragma unroll
            for (int mt = 0; mt < 4; mt++) {
                uint32_t ad = abase + a_lane_off + mt * (16 * 80) + k16 * 32;
                ldsm_x4(af[mt][0], af[mt][1], af[mt][2], af[mt][3], ad);
            }
            #pragma unroll
            for (int nt = 0; nt < 4; nt++) {
                uint32_t bd = abase + b_lane_off + nt * (8 * 80) + k16 * 32;
                ldsm_x2(bf[nt][0], bf[nt][1], bd);
            }
            #pragma unroll
            for (int mt = 0; mt < 4; mt++)
                #pragma unroll
                for (int nt = 0; nt < 4; nt++)
                    mma16816(acc[mt][nt][0], acc[mt][nt][1],
                             acc[mt][nt][2], acc[mt][nt][3],
                             af[mt][0], af[mt][1], af[mt][2], af[mt][3],
                             bf[nt][0], bf[nt][1]);
        }
        __syncthreads();
    }

    // epilogue: row m = t*32+b  ->  out[b][t][col], add bias
    #pragma unroll
    for (int mt = 0; mt < 4; mt++) {
        #pragma unroll
        for (int nt = 0; nt < 4; nt++) {
            int col = ntb * 128 + wn + nt * 8 + (lane & 3) * 2;
            if (col < VV) {
                float bb0 = __ldg(bv + col);
                float bb1 = __ldg(bv + col + 1);
                int m0 = mtb * 128 + wm + mt * 16 + (lane >> 2);
                int bI = m0 & 31, tI = m0 >> 5;
                float2 v0 = { acc[mt][nt][0] + bb0, acc[mt][nt][1] + bb1 };
                *(float2*)(out + (size_t)bI * TT * VV + (size_t)tI * VV + col) = v0;
                int m1 = m0 + 8;
                bI = m1 & 31; tI = m1 >> 5;
                float2 v1 = { acc[mt][nt][2] + bb0, acc[mt][nt][3] + bb1 };
                *(float2*)(out + (size_t)bI * TT * VV + (size_t)tI * VV + col) = v1;
            }
        }
    }
}

// ------------------------------------------------------------------
extern "C" void kernel_launch(void* const* d_in, const int* in_sizes, int n_in,
                              void* d_out, int out_size)
{
    const float* tv    = (const float*)d_in[0];
    const int*   texts = (const int*)  d_in[1];
    const int*   start = (const int*)  d_in[3];
    const float* emb   = (const float*)d_in[4];
    const float* W_ih  = (const float*)d_in[5];
    const float* b_ih  = (const float*)d_in[6];
    const float* W_hh  = (const float*)d_in[7];
    const float* b_hh  = (const float*)d_in[8];
    const float* Wo_w  = (const float*)d_in[9];
    const float* Wo_b  = (const float*)d_in[10];
    const float* Wh_w  = (const float*)d_in[11];
    const float* Wh_b  = (const float*)d_in[12];
    const float* Wc_w  = (const float*)d_in[13];
    const float* Wc_b  = (const float*)d_in[14];
    const float* Wv_w  = (const float*)d_in[15];
    const float* Wv_b  = (const float*)d_in[16];
    float* out = (float*)d_out;

    const int lstm_smem = (16 * 512 + 64 * 32 * 4 + 16 * 32 + 4 * 32) * 4;
    cudaFuncSetAttribute(k_lstm, cudaFuncAttributeMaxDynamicSharedMemorySize, 69632);

    k_init<<<6144, 256>>>(tv, Wo_w, Wo_b, Wh_w, Wh_b, Wc_w, Wc_b);
    k_base<<<8192, 256>>>(tv, W_ih, b_ih, b_hh);
    k_gather<<<TT * BQ, 64>>>(emb, texts, start);
    k_convW<<<(G4 * EE) / 1024, 256>>>(W_ih);
    k_convB<<<(VPAD * HH) / 256, 256>>>(Wv_w);
    k_G_mma<<<dim3(G4 / 128, (TT * BQ) / 128), 256>>>();
    k_lstm<<<128, 256, lstm_smem>>>(W_hh);
    k_convA<<<(TT * BQ * HH) / 256, 256>>>();
    k_logits_mma<<<dim3(VPAD / 128, (TT * BQ) / 128), 256>>>(Wv_b, out);
}

// round 8
// speedup vs baseline: 2.8411x; 2.2604x over previous
#include <cuda_runtime.h>
#include <cuda_bf16.h>
#include <cuda_fp16.h>
#include <cstdint>
#include <math.h>

#define BQ   32
#define TT   128
#define EE   256
#define HH   512
#define ENCC 512
#define VV   10000
#define G4   2048          // 4*H
#define XW   1280          // E + H + ENC
#define VPAD 10112         // 79 * 128

// ------------------------------------------------------------------
// scratch (static device globals; no allocations allowed)
// ------------------------------------------------------------------
__device__ float g_o[BQ * HH];
__device__ float g_c0[BQ * HH];
__device__ float g_base[BQ * G4];
__device__ float g_G[TT * BQ * G4];               // per-step gate input (32 MB)
__device__ unsigned g_bar_count;
__device__ unsigned g_bar_gen;

// fp16 operands
__device__ __half g_h16[(TT + 1) * BQ * HH];      // slot0=h0, slot t+1 = h after step t (fp16)
__device__ __half g_Bh[VPAD * HH];                // logits B (Wv) fp16, 10 MB
__device__ __half g_E[TT * BQ * EE];              // gathered prev-token embeddings
__device__ __half g_Wih16[G4 * EE];               // W_ih[:, :E] fp16
__device__ __half g_Whh16[G4 * HH];               // W_hh fp16, 2 MB

// ------------------------------------------------------------------
// kernel 1: o, h0, c0   (warp per output, shuffle reduce)
// ------------------------------------------------------------------
__global__ void k_init(const float* __restrict__ tv,
                       const float* __restrict__ Wo, const float* __restrict__ bo,
                       const float* __restrict__ Wh, const float* __restrict__ bh,
                       const float* __restrict__ Wc, const float* __restrict__ bc)
{
    int warp = (blockIdx.x * blockDim.x + threadIdx.x) >> 5;
    int lane = threadIdx.x & 31;
    if (warp >= 3 * BQ * HH) return;
    int m   = warp / (BQ * HH);
    int rem = warp % (BQ * HH);
    int b = rem / HH, j = rem % HH;
    const float* W    = (m == 0) ? Wo : (m == 1) ? Wh : Wc;
    const float* bias = (m == 0) ? bo : (m == 1) ? bh : bc;
    const float* x = tv + b * ENCC;
    const float* w = W  + j * ENCC;
    float s = 0.f;
    for (int k = lane; k < ENCC; k += 32) s += x[k] * w[k];
    #pragma unroll
    for (int o = 16; o; o >>= 1) s += __shfl_xor_sync(0xffffffffu, s, o);
    if (lane == 0) {
        float v = s + bias[j];
        if (m == 0)      g_o[b * HH + j]   = v;
        else if (m == 1) g_h16[b * HH + j] = __float2half_rn(v);   // slot 0 = h0
        else             g_c0[b * HH + j]  = v;
    }
}

// ------------------------------------------------------------------
// kernel 2: gates_base
// ------------------------------------------------------------------
__global__ void k_base(const float* __restrict__ tv,
                       const float* __restrict__ W_ih,
                       const float* __restrict__ b_ih,
                       const float* __restrict__ b_hh)
{
    int warp = (blockIdx.x * blockDim.x + threadIdx.x) >> 5;
    int lane = threadIdx.x & 31;
    if (warp >= BQ * G4) return;
    int b = warp / G4, n = warp % G4;
    const float* w = W_ih + (size_t)n * XW + EE;
    float s = 0.f;
    for (int k = lane; k < HH + ENCC; k += 32) {
        float x = (k < HH) ? g_o[b * HH + k] : tv[b * ENCC + (k - HH)];
        s += x * w[k];
    }
    #pragma unroll
    for (int o = 16; o; o >>= 1) s += __shfl_xor_sync(0xffffffffu, s, o);
    if (lane == 0) g_base[b * G4 + n] = s + b_ih[n] + b_hh[n];
}

// ------------------------------------------------------------------
// kernel 3a: gather prev-token embeddings as dense fp16 A [4096 x 256]
// ------------------------------------------------------------------
__global__ void k_gather(const float* __restrict__ emb,
                         const int*   __restrict__ texts,
                         const int*   __restrict__ startp)
{
    int r = blockIdx.x;                 // 0..4095
    int t = r >> 5, b = r & 31;
    int tok = (t == 0) ? startp[0] : texts[b * TT + t - 1];
    const float* src = emb + (size_t)tok * EE;
    int k = threadIdx.x * 4;            // 64 threads x 4
    float4 v = *(const float4*)(src + k);
    __half2 h0 = __floats2half2_rn(v.x, v.y);
    __half2 h1 = __floats2half2_rn(v.z, v.w);
    *(__half2*)(g_E + (size_t)r * EE + k)     = h0;
    *(__half2*)(g_E + (size_t)r * EE + k + 2) = h1;
}

// ------------------------------------------------------------------
// kernel 3b: W_ih[:, :E] -> fp16 [2048 x 256]
// ------------------------------------------------------------------
__global__ void k_convW(const float* __restrict__ W_ih)
{
    int e = (blockIdx.x * 256 + threadIdx.x) * 4;
    int n = e >> 8, k = e & 255;
    float4 v = *(const float4*)(W_ih + (size_t)n * XW + k);
    *(__half2*)(g_Wih16 + (size_t)n * EE + k)     = __floats2half2_rn(v.x, v.y);
    *(__half2*)(g_Wih16 + (size_t)n * EE + k + 2) = __floats2half2_rn(v.z, v.w);
}

// ------------------------------------------------------------------
// kernel 3c: W_hh -> fp16 [2048 x 512] (contiguous)
// ------------------------------------------------------------------
__global__ void k_convWhh(const float* __restrict__ W_hh)
{
    int e = (blockIdx.x * 256 + threadIdx.x) * 4;   // over 2048*512
    float4 v = *(const float4*)(W_hh + e);
    *(__half2*)(g_Whh16 + e)     = __floats2half2_rn(v.x, v.y);
    *(__half2*)(g_Whh16 + e + 2) = __floats2half2_rn(v.z, v.w);
}

// ------------------------------------------------------------------
// kernel 3d: Wv -> fp16 (padded)
// ------------------------------------------------------------------
__global__ void k_convB(const float* __restrict__ Wv)
{
    size_t idx = (size_t)blockIdx.x * 256 + threadIdx.x;   // VPAD*HH
    int n = (int)(idx >> 9);
    float x = (n < VV) ? Wv[idx] : 0.f;
    g_Bh[idx] = __float2half_rn(x);
}

// ------------------------------------------------------------------
// mma / ldmatrix / cp.async helpers
// ------------------------------------------------------------------
__device__ __forceinline__ void cp_async16(uint32_t dst, const void* src)
{
    asm volatile("cp.async.cg.shared.global [%0], [%1], 16;" :: "r"(dst), "l"(src));
}
__device__ __forceinline__ void cp_commit()
{
    asm volatile("cp.async.commit_group;");
}
__device__ __forceinline__ void cp_wait_all()
{
    asm volatile("cp.async.wait_group 0;");
}
__device__ __forceinline__ void ldsm_x4(uint32_t& r0, uint32_t& r1,
                                        uint32_t& r2, uint32_t& r3, uint32_t addr)
{
    asm volatile("ldmatrix.sync.aligned.m8n8.x4.shared.b16 {%0,%1,%2,%3}, [%4];"
                 : "=r"(r0), "=r"(r1), "=r"(r2), "=r"(r3) : "r"(addr));
}
__device__ __forceinline__ void ldsm_x2(uint32_t& r0, uint32_t& r1, uint32_t addr)
{
    asm volatile("ldmatrix.sync.aligned.m8n8.x2.shared.b16 {%0,%1}, [%2];"
                 : "=r"(r0), "=r"(r1) : "r"(addr));
}
__device__ __forceinline__ void mma16816(float& c0, float& c1, float& c2, float& c3,
                                         uint32_t a0, uint32_t a1, uint32_t a2, uint32_t a3,
                                         uint32_t b0, uint32_t b1)
{
    asm volatile("mma.sync.aligned.m16n8k16.row.col.f32.f16.f16.f32 "
                 "{%0,%1,%2,%3}, {%4,%5,%6,%7}, {%8,%9}, {%0,%1,%2,%3};"
                 : "+f"(c0), "+f"(c1), "+f"(c2), "+f"(c3)
                 : "r"(a0), "r"(a1), "r"(a2), "r"(a3), "r"(b0), "r"(b1));
}

__device__ __forceinline__ float fsigm(float x)
{
    x = fminf(fmaxf(x, -30.f), 30.f);
    return __fdividef(1.f, 1.f + __expf(-x));
}
__device__ __forceinline__ float ftanh(float x)
{
    x = fminf(fmaxf(x, -15.f), 15.f);
    float e = __expf(2.f * x);
    return __fdividef(e - 1.f, e + 1.f);
}

// ------------------------------------------------------------------
// kernel 4: sequential LSTM via HMMA (persistent, 128 CTAs x 128 thr)
// CTA p owns h-indices [4p,4p+4) => 16 gate rows. Per step:
//   C[16x32] = Wslice[16x512] @ h[512x32]  (fp16 MMA, fp32 accum)
// warp w handles batch cols 8w..8w+7 (one n8 tile), 32 k-steps.
// c-state in registers of lanes 0-15; h written as fp16 to g_h16.
// SMEM: sW 16x520h (16640B) | sH 32x520h (33280B) | sG 16x33 f32 (2112B)
// ------------------------------------------------------------------
#define SW_OFF 0
#define SH_OFF 16640
#define SG_OFF 49920
#define LSTM_SMEM 53248

__global__ void __launch_bounds__(128, 1) k_lstm()
{
    extern __shared__ __align__(16) char smem[];
    uint32_t sbase = (uint32_t)__cvta_generic_to_shared(smem);
    float* sG = (float*)(smem + SG_OFF);
    __shared__ unsigned sGen;

    const int tid  = threadIdx.x;
    const int lane = tid & 31;
    const int w    = tid >> 5;          // warp 0..3
    const int p    = blockIdx.x;        // 0..127

    // ---- load W slice (16 rows x 512 halves) into SMEM ----
    // row lr -> W_hh row n = (lr>>2)*512 + p*4 + (lr&3)
    for (int i = 0; i < 8; i++) {
        int idx = tid + i * 128;        // 0..1023
        int lr = idx >> 6, seg = idx & 63;
        int n  = (lr >> 2) * HH + p * 4 + (lr & 3);
        cp_async16(sbase + SW_OFF + lr * 1040 + seg * 16,
                   g_Whh16 + (size_t)n * HH + seg * 8);
    }
    cp_commit(); cp_wait_all();

    // ---- c state in registers (lanes 0-15 of each warp) ----
    const int q    = lane >> 2;                 // 0..7 (valid gate q for lanes<16)
    const int colb = w * 8 + (lane & 3) * 2;    // batch pair base
    float cs0 = 0.f, cs1 = 0.f;
    if (lane < 16) {
        cs0 = g_c0[colb * HH + p * 4 + q];
        cs1 = g_c0[(colb + 1) * HH + p * 4 + q];
    }

    if (tid == 0) sGen = g_bar_gen;
    __syncthreads();
    const unsigned base_gen = sGen;

    // ldmatrix lane offsets
    const int amat = lane >> 3;
    const uint32_t aoff = sbase + SW_OFF
        + (uint32_t)(((amat & 1) * 8 + (lane & 7)) * 1040 + ((amat >> 1) * 8) * 2);
    const uint32_t boff = sbase + SH_OFF
        + (uint32_t)((w * 8 + (lane & 7)) * 1040 + (lane >> 3) * 16);

    for (int t = 0; t < TT; t++) {
        // ---- stage G tile: 128 threads, (b = tid&31, gate = tid>>5) ----
        {
            int b = tid & 31, g = tid >> 5;
            float4 v = __ldcg((const float4*)(g_G + (size_t)(t * BQ + b) * G4
                                              + g * HH + p * 4));
            sG[(g * 4 + 0) * 33 + b] = v.x;
            sG[(g * 4 + 1) * 33 + b] = v.y;
            sG[(g * 4 + 2) * 33 + b] = v.z;
            sG[(g * 4 + 3) * 33 + b] = v.w;
        }

        // ---- stage this warp's 8 h rows (8 KB) ----
        {
            const __half* hsrc = g_h16 + (size_t)t * (BQ * HH);
            #pragma unroll
            for (int j = 0; j < 16; j++) {
                int idx = lane + j * 32;        // 0..511
                int row = idx >> 6, seg = idx & 63;
                cp_async16(sbase + SH_OFF + (w * 8 + row) * 1040 + seg * 16,
                           hsrc + (size_t)(w * 8 + row) * HH + seg * 8);
            }
            cp_commit(); cp_wait_all();
            __syncwarp();
        }

        // ---- MMA: 32 k-steps, 4 interleaved accumulator sets ----
        float acc[4][4];
        #pragma unroll
        for (int s = 0; s < 4; s++)
            { acc[s][0] = 0.f; acc[s][1] = 0.f; acc[s][2] = 0.f; acc[s][3] = 0.f; }

        #pragma unroll
        for (int i = 0; i < 16; i++) {          // i covers k-steps 2i, 2i+1
            uint32_t b0, b1, b2, b3;
            ldsm_x4(b0, b1, b2, b3, boff + i * 64);   // 32 halves = 64 B
            uint32_t a0, a1, a2, a3;
            ldsm_x4(a0, a1, a2, a3, aoff + (2 * i) * 32);
            int s0 = (2 * i) & 3;
            mma16816(acc[s0][0], acc[s0][1], acc[s0][2], acc[s0][3],
                     a0, a1, a2, a3, b0, b1);
            ldsm_x4(a0, a1, a2, a3, aoff + (2 * i + 1) * 32);
            int s1 = (2 * i + 1) & 3;
            mma16816(acc[s1][0], acc[s1][1], acc[s1][2], acc[s1][3],
                     a0, a1, a2, a3, b2, b3);
        }
        float g0 = (acc[0][0] + acc[1][0]) + (acc[2][0] + acc[3][0]);
        float g1 = (acc[0][1] + acc[1][1]) + (acc[2][1] + acc[3][1]);
        float g2 = (acc[0][2] + acc[1][2]) + (acc[2][2] + acc[3][2]);
        float g3 = (acc[0][3] + acc[1][3]) + (acc[2][3] + acc[3][3]);

        __syncthreads();   // sG staged by all threads

        // ---- add G ----
        int r0 = lane >> 2;                     // frag row (0..7)
        g0 += sG[r0 * 33 + colb];
        g1 += sG[r0 * 33 + colb + 1];
        g2 += sG[(r0 + 8) * 33 + colb];
        g3 += sG[(r0 + 8) * 33 + colb + 1];

        // ---- exchange f/o (lanes 16-31) -> i/g holders (lanes 0-15) ----
        float f0 = __shfl_xor_sync(0xffffffffu, g0, 16);
        float f1 = __shfl_xor_sync(0xffffffffu, g1, 16);
        float o0 = __shfl_xor_sync(0xffffffffu, g2, 16);
        float o1 = __shfl_xor_sync(0xffffffffu, g3, 16);

        if (lane < 16) {
            // lanes 0-15: g0/g1 = i-gate, g2/g3 = g-gate, f*/o* received
            float i0 = fsigm(g0), i1 = fsigm(g1);
            float t0 = ftanh(g2), t1 = ftanh(g3);
            float F0 = fsigm(f0), F1 = fsigm(f1);
            float O0 = fsigm(o0), O1 = fsigm(o1);
            cs0 = F0 * cs0 + i0 * t0;
            cs1 = F1 * cs1 + i1 * t1;
            float h0 = O0 * ftanh(cs0);
            float h1 = O1 * ftanh(cs1);
            size_t hb = (size_t)(t + 1) * (BQ * HH) + p * 4 + q;
            g_h16[hb + (size_t)colb * HH]       = __float2half_rn(h0);
            g_h16[hb + (size_t)(colb + 1) * HH] = __float2half_rn(h1);
        }

        // ---- grid barrier ----
        __threadfence();
        __syncthreads();
        if (tid == 0) {
            unsigned target = base_gen + (unsigned)(t + 1);
            unsigned arr = atomicAdd(&g_bar_count, 1u);
            if (arr == 127u) {
                g_bar_count = 0u;
                __threadfence();
                atomicExch(&g_bar_gen, target);
            } else {
                volatile unsigned* vg = &g_bar_gen;
                while (*vg < target) { }
            }
            __threadfence();
        }
        __syncthreads();
    }
}

#define MMA_SMEM_BUF 20480           // A(10240) + B(10240) per buffer

// ------------------------------------------------------------------
// kernel 5: G = E @ Wih^T + base  (fp16 HMMA, K=256)
// ------------------------------------------------------------------
__device__ __forceinline__ void g_load_tile(
    int kt, int buf, int tid, int mtb, int ntb, uint32_t sbase)
{
    const int k0 = kt * 32;
    const uint32_t abase = sbase + buf * MMA_SMEM_BUF;
    const uint32_t bbase = abase + 10240;
    #pragma unroll
    for (int i = 0; i < 2; i++) {
        int ch  = tid + i * 256;
        int row = ch >> 2, kc = ch & 3;
        cp_async16(abase + row * 80 + kc * 16,
                   g_E + (size_t)(mtb * 128 + row) * EE + k0 + kc * 8);
        cp_async16(bbase + row * 80 + kc * 16,
                   g_Wih16 + (size_t)(ntb * 128 + row) * EE + k0 + kc * 8);
    }
    cp_commit();
}

__global__ void __launch_bounds__(256) k_G_mma()
{
    __shared__ __align__(16) unsigned char smem[2 * MMA_SMEM_BUF];
    const int tid  = threadIdx.x;
    const int lane = tid & 31;
    const int warp = tid >> 5;
    const int ntb  = blockIdx.x;     // 0..15
    const int mtb  = blockIdx.y;     // 0..31

    const int wm = (warp >> 2) * 64;
    const int wn = (warp & 3) * 32;

    uint32_t sbase = (uint32_t)__cvta_generic_to_shared(smem);

    float acc[4][4][4];
    #pragma unroll
    for (int i = 0; i < 4; i++)
        #pragma unroll
        for (int j = 0; j < 4; j++) {
            acc[i][j][0] = 0.f; acc[i][j][1] = 0.f;
            acc[i][j][2] = 0.f; acc[i][j][3] = 0.f;
        }

    const int amat  = lane >> 3;
    const uint32_t a_lane_off = (uint32_t)((wm + (amat & 1) * 8 + (lane & 7)) * 80
                                           + ((amat >> 1) * 8) * 2);
    const int blane = lane & 15;
    const uint32_t b_lane_off = (uint32_t)(10240 + (wn + (blane & 7)) * 80
                                           + ((blane >> 3) * 8) * 2);

    const int NKT = 8;                         // 256 / 32
    g_load_tile(0, 0, tid, mtb, ntb, sbase);

    for (int kt = 0; kt < NKT; kt++) {
        if (kt + 1 < NKT) {
            g_load_tile(kt + 1, (kt + 1) & 1, tid, mtb, ntb, sbase);
            asm volatile("cp.async.wait_group 1;");
        } else {
            asm volatile("cp.async.wait_group 0;");
        }
        __syncthreads();

        const uint32_t abase = sbase + (kt & 1) * MMA_SMEM_BUF;
        #pragma unroll
        for (int k16 = 0; k16 < 2; k16++) {
            uint32_t af[4][4];
            uint32_t bf[4][2];
            #pragma unroll
            for (int mt = 0; mt < 4; mt++) {
                uint32_t ad = abase + a_lane_off + mt * (16 * 80) + k16 * 32;
                ldsm_x4(af[mt][0], af[mt][1], af[mt][2], af[mt][3], ad);
            }
            #pragma unroll
            for (int nt = 0; nt < 4; nt++) {
                uint32_t bd = abase + b_lane_off + nt * (8 * 80) + k16 * 32;
                ldsm_x2(bf[nt][0], bf[nt][1], bd);
            }
            #pragma unroll
            for (int mt = 0; mt < 4; mt++)
                #pragma unroll
                for (int nt = 0; nt < 4; nt++)
                    mma16816(acc[mt][nt][0], acc[mt][nt][1],
                             acc[mt][nt][2], acc[mt][nt][3],
                             af[mt][0], af[mt][1], af[mt][2], af[mt][3],
                             bf[nt][0], bf[nt][1]);
        }
        __syncthreads();
    }

    #pragma unroll
    for (int mt = 0; mt < 4; mt++) {
        #pragma unroll
        for (int nt = 0; nt < 4; nt++) {
            int col = ntb * 128 + wn + nt * 8 + (lane & 3) * 2;
            int m0 = mtb * 128 + wm + mt * 16 + (lane >> 2);
            float2 bs0 = *(const float2*)&g_base[(m0 & 31) * G4 + col];
            float2 v0 = { acc[mt][nt][0] + bs0.x, acc[mt][nt][1] + bs0.y };
            *(float2*)&g_G[(size_t)m0 * G4 + col] = v0;
            int m1 = m0 + 8;
            float2 bs1 = *(const float2*)&g_base[(m1 & 31) * G4 + col];
            float2 v1 = { acc[mt][nt][2] + bs1.x, acc[mt][nt][3] + bs1.y };
            *(float2*)&g_G[(size_t)m1 * G4 + col] = v1;
        }
    }
}

// ------------------------------------------------------------------
// kernel 6: logits via fp16 HMMA, single pass (K = 512)
// A = g_h16 + 32*512 (row r = t*32+b -> hs[t])
// ------------------------------------------------------------------
__device__ __forceinline__ void logits_load_tile(
    int kt, int buf, int tid, int mtb, int ntb, uint32_t sbase)
{
    const int k0 = kt * 32;
    const __half* A = g_h16 + BQ * HH;
    const uint32_t abase = sbase + buf * MMA_SMEM_BUF;
    const uint32_t bbase = abase + 10240;
    #pragma unroll
    for (int i = 0; i < 2; i++) {
        int ch  = tid + i * 256;
        int row = ch >> 2, kc = ch & 3;
        cp_async16(abase + row * 80 + kc * 16,
                   A + (size_t)(mtb * 128 + row) * HH + k0 + kc * 8);
        cp_async16(bbase + row * 80 + kc * 16,
                   g_Bh + (size_t)(ntb * 128 + row) * HH + k0 + kc * 8);
    }
    cp_commit();
}

__global__ void __launch_bounds__(256) k_logits_mma(const float* __restrict__ bv,
                                                    float* __restrict__ out)
{
    __shared__ __align__(16) unsigned char smem[2 * MMA_SMEM_BUF];
    const int tid  = threadIdx.x;
    const int lane = tid & 31;
    const int warp = tid >> 5;
    const int ntb  = blockIdx.x;     // 0..78
    const int mtb  = blockIdx.y;     // 0..31

    const int wm = (warp >> 2) * 64;
    const int wn = (warp & 3) * 32;

    uint32_t sbase = (uint32_t)__cvta_generic_to_shared(smem);

    float acc[4][4][4];
    #pragma unroll
    for (int i = 0; i < 4; i++)
        #pragma unroll
        for (int j = 0; j < 4; j++) {
            acc[i][j][0] = 0.f; acc[i][j][1] = 0.f;
            acc[i][j][2] = 0.f; acc[i][j][3] = 0.f;
        }

    const int amat  = lane >> 3;
    const uint32_t a_lane_off = (uint32_t)((wm + (amat & 1) * 8 + (lane & 7)) * 80
                                           + ((amat >> 1) * 8) * 2);
    const int blane = lane & 15;
    const uint32_t b_lane_off = (uint32_t)(10240 + (wn + (blane & 7)) * 80
                                           + ((blane >> 3) * 8) * 2);

    const int NKT = 16;                        // 512 / 32
    logits_load_tile(0, 0, tid, mtb, ntb, sbase);

    for (int kt = 0; kt < NKT; kt++) {
        if (kt + 1 < NKT) {
            logits_load_tile(kt + 1, (kt + 1) & 1, tid, mtb, ntb, sbase);
            asm volatile("cp.async.wait_group 1;");
        } else {
            asm volatile("cp.async.wait_group 0;");
        }
        __syncthreads();

        const uint32_t abase = sbase + (kt & 1) * MMA_SMEM_BUF;
        #pragma unroll
        for (int k16 = 0; k16 < 2; k16++) {
            uint32_t af[4][4];
            uint32_t bf[4][2];
            #pragma unroll
            for (int mt = 0; mt < 4; mt++) {
                uint32_t ad = abase + a_lane_off + mt * (16 * 80) + k16 * 32;
                ldsm_x4(af[mt][0], af[mt][1], af[mt][2], af[mt][3], ad);
            }
            #pragma unroll
            for (int nt = 0; nt < 4; nt++) {
                uint32_t bd = abase + b_lane_off + nt * (8 * 80) + k16 * 32;
                ldsm_x2(bf[nt][0], bf[nt][1], bd);
            }
            #pragma unroll
            for (int mt = 0; mt < 4; mt++)
                #pragma unroll
                for (int nt = 0; nt < 4; nt++)
                    mma16816(acc[mt][nt][0], acc[mt][nt][1],
                             acc[mt][nt][2], acc[mt][nt][3],
                             af[mt][0], af[mt][1], af[mt][2], af[mt][3],
                             bf[nt][0], bf[nt][1]);
        }
        __syncthreads();
    }

    #pragma unroll
    for (int mt = 0; mt < 4; mt++) {
        #pragma unroll
        for (int nt = 0; nt < 4; nt++) {
            int col = ntb * 128 + wn + nt * 8 + (lane & 3) * 2;
            if (col < VV) {
                float bb0 = __ldg(bv + col);
                float bb1 = __ldg(bv + col + 1);
                int m0 = mtb * 128 + wm + mt * 16 + (lane >> 2);
                int bI = m0 & 31, tI = m0 >> 5;
                float2 v0 = { acc[mt][nt][0] + bb0, acc[mt][nt][1] + bb1 };
                *(float2*)(out + (size_t)bI * TT * VV + (size_t)tI * VV + col) = v0;
                int m1 = m0 + 8;
                bI = m1 & 31; tI = m1 >> 5;
                float2 v1 = { acc[mt][nt][2] + bb0, acc[mt][nt][3] + bb1 };
                *(float2*)(out + (size_t)bI * TT * VV + (size_t)tI * VV + col) = v1;
            }
        }
    }
}

// ------------------------------------------------------------------
extern "C" void kernel_launch(void* const* d_in, const int* in_sizes, int n_in,
                              void* d_out, int out_size)
{
    const float* tv    = (const float*)d_in[0];
    const int*   texts = (const int*)  d_in[1];
    const int*   start = (const int*)  d_in[3];
    const float* emb   = (const float*)d_in[4];
    const float* W_ih  = (const float*)d_in[5];
    const float* b_ih  = (const float*)d_in[6];
    const float* W_hh  = (const float*)d_in[7];
    const float* b_hh  = (const float*)d_in[8];
    const float* Wo_w  = (const float*)d_in[9];
    const float* Wo_b  = (const float*)d_in[10];
    const float* Wh_w  = (const float*)d_in[11];
    const float* Wh_b  = (const float*)d_in[12];
    const float* Wc_w  = (const float*)d_in[13];
    const float* Wc_b  = (const float*)d_in[14];
    const float* Wv_w  = (const float*)d_in[15];
    const float* Wv_b  = (const float*)d_in[16];
    float* out = (float*)d_out;

    cudaFuncSetAttribute(k_lstm, cudaFuncAttributeMaxDynamicSharedMemorySize, LSTM_SMEM);

    k_init<<<6144, 256>>>(tv, Wo_w, Wo_b, Wh_w, Wh_b, Wc_w, Wc_b);
    k_base<<<8192, 256>>>(tv, W_ih, b_ih, b_hh);
    k_gather<<<TT * BQ, 64>>>(emb, texts, start);
    k_convW<<<(G4 * EE) / 1024, 256>>>(W_ih);
    k_convWhh<<<(G4 * HH) / 1024, 256>>>(W_hh);
    k_convB<<<(VPAD * HH) / 256, 256>>>(Wv_w);
    k_G_mma<<<dim3(G4 / 128, (TT * BQ) / 128), 256>>>();
    k_lstm<<<128, 128, LSTM_SMEM>>>();
    k_logits_mma<<<dim3(VPAD / 128, (TT * BQ) / 128), 256>>>(Wv_b, out);
}

// round 9
// speedup vs baseline: 2.9862x; 1.0511x over previous
#include <cuda_runtime.h>
#include <cuda_bf16.h>
#include <cuda_fp16.h>
#include <cstdint>
#include <math.h>

#define BQ   32
#define TT   128
#define EE   256
#define HH   512
#define ENCC 512
#define VV   10000
#define G4   2048          // 4*H
#define XW   1280          // E + H + ENC
#define VPAD 10112         // 79 * 128

// ------------------------------------------------------------------
// scratch (static device globals; no allocations allowed)
// ------------------------------------------------------------------
__device__ float g_o[BQ * HH];
__device__ float g_c0[BQ * HH];
__device__ float g_base[BQ * G4];
__device__ float g_G[TT * BQ * G4];               // per-step gate input (32 MB)
__device__ unsigned g_bar_count;
__device__ unsigned g_bar_gen;

// fp16 operands
__device__ __half g_h16[(TT + 1) * BQ * HH];      // slot0=h0, slot t+1 = h after step t
__device__ __half g_Bh[VPAD * HH];                // logits B (Wv) fp16
__device__ __half g_E[TT * BQ * EE];              // gathered prev-token embeddings
__device__ __half g_Wih16[G4 * EE];               // W_ih[:, :E] fp16
__device__ __half g_Wihb[G4 * 1024];              // W_ih[:, E:] fp16 (cols 256..1279)
__device__ __half g_Whh16[G4 * HH];               // W_hh fp16
__device__ __half g_X16[128 * 1024];              // [o|tv] fp16, rows 32..127 stay zero

// ------------------------------------------------------------------
// kernel 1: o, h0, c0   (warp per output, shuffle reduce)
// ------------------------------------------------------------------
__global__ void k_init(const float* __restrict__ tv,
                       const float* __restrict__ Wo, const float* __restrict__ bo,
                       const float* __restrict__ Wh, const float* __restrict__ bh,
                       const float* __restrict__ Wc, const float* __restrict__ bc)
{
    int warp = (blockIdx.x * blockDim.x + threadIdx.x) >> 5;
    int lane = threadIdx.x & 31;
    if (warp >= 3 * BQ * HH) return;
    int m   = warp / (BQ * HH);
    int rem = warp % (BQ * HH);
    int b = rem / HH, j = rem % HH;
    const float* W    = (m == 0) ? Wo : (m == 1) ? Wh : Wc;
    const float* bias = (m == 0) ? bo : (m == 1) ? bh : bc;
    const float* x = tv + b * ENCC;
    const float* w = W  + j * ENCC;
    float s = 0.f;
    for (int k = lane; k < ENCC; k += 32) s += x[k] * w[k];
    #pragma unroll
    for (int o = 16; o; o >>= 1) s += __shfl_xor_sync(0xffffffffu, s, o);
    if (lane == 0) {
        float v = s + bias[j];
        if (m == 0)      g_o[b * HH + j]   = v;
        else if (m == 1) g_h16[b * HH + j] = __float2half_rn(v);   // slot 0 = h0
        else             g_c0[b * HH + j]  = v;
    }
}

// ------------------------------------------------------------------
// kernel 2a: pack A = [o | tv] fp16 into g_X16 rows 0..31
// ------------------------------------------------------------------
__global__ void k_packX(const float* __restrict__ tv)
{
    int e = (blockIdx.x * 256 + threadIdx.x) * 2;    // 0..32767 elems (32x1024)
    int b = e >> 10, c = e & 1023;
    float v0, v1;
    if (c < 512) { v0 = g_o[b * HH + c];        v1 = g_o[b * HH + c + 1]; }
    else         { v0 = tv[b * ENCC + c - 512]; v1 = tv[b * ENCC + c - 511]; }
    *(__half2*)(g_X16 + b * 1024 + c) = __floats2half2_rn(v0, v1);
}

// ------------------------------------------------------------------
// kernel 3a: gather prev-token embeddings as dense fp16 A [4096 x 256]
// ------------------------------------------------------------------
__global__ void k_gather(const float* __restrict__ emb,
                         const int*   __restrict__ texts,
                         const int*   __restrict__ startp)
{
    int r = blockIdx.x;                 // 0..4095
    int t = r >> 5, b = r & 31;
    int tok = (t == 0) ? startp[0] : texts[b * TT + t - 1];
    const float* src = emb + (size_t)tok * EE;
    int k = threadIdx.x * 4;            // 64 threads x 4
    float4 v = *(const float4*)(src + k);
    *(__half2*)(g_E + (size_t)r * EE + k)     = __floats2half2_rn(v.x, v.y);
    *(__half2*)(g_E + (size_t)r * EE + k + 2) = __floats2half2_rn(v.z, v.w);
}

// ------------------------------------------------------------------
// kernel 3b: W_ih[:, :E] -> fp16 [2048 x 256]
// ------------------------------------------------------------------
__global__ void k_convW(const float* __restrict__ W_ih)
{
    int e = (blockIdx.x * 256 + threadIdx.x) * 4;
    int n = e >> 8, k = e & 255;
    float4 v = *(const float4*)(W_ih + (size_t)n * XW + k);
    *(__half2*)(g_Wih16 + (size_t)n * EE + k)     = __floats2half2_rn(v.x, v.y);
    *(__half2*)(g_Wih16 + (size_t)n * EE + k + 2) = __floats2half2_rn(v.z, v.w);
}

// ------------------------------------------------------------------
// kernel 3b2: W_ih[:, E:] -> fp16 [2048 x 1024]
// ------------------------------------------------------------------
__global__ void k_convWb(const float* __restrict__ W_ih)
{
    int e = (blockIdx.x * 256 + threadIdx.x) * 4;   // over 2048*1024
    int n = e >> 10, k = e & 1023;
    float4 v = *(const float4*)(W_ih + (size_t)n * XW + EE + k);
    *(__half2*)(g_Wihb + (size_t)n * 1024 + k)     = __floats2half2_rn(v.x, v.y);
    *(__half2*)(g_Wihb + (size_t)n * 1024 + k + 2) = __floats2half2_rn(v.z, v.w);
}

// ------------------------------------------------------------------
// kernel 3c: W_hh -> fp16 [2048 x 512]
// ------------------------------------------------------------------
__global__ void k_convWhh(const float* __restrict__ W_hh)
{
    int e = (blockIdx.x * 256 + threadIdx.x) * 4;   // over 2048*512
    float4 v = *(const float4*)(W_hh + e);
    *(__half2*)(g_Whh16 + e)     = __floats2half2_rn(v.x, v.y);
    *(__half2*)(g_Whh16 + e + 2) = __floats2half2_rn(v.z, v.w);
}

// ------------------------------------------------------------------
// kernel 3d: Wv -> fp16 (padded), 4 elems/thread
// ------------------------------------------------------------------
__global__ void k_convB(const float* __restrict__ Wv)
{
    size_t e = ((size_t)blockIdx.x * 256 + threadIdx.x) * 4;   // VPAD*HH
    int n = (int)(e >> 9);
    if (n < VV) {
        float4 v = *(const float4*)(Wv + e);
        *(__half2*)(g_Bh + e)     = __floats2half2_rn(v.x, v.y);
        *(__half2*)(g_Bh + e + 2) = __floats2half2_rn(v.z, v.w);
    } else {
        *(__half2*)(g_Bh + e)     = __floats2half2_rn(0.f, 0.f);
        *(__half2*)(g_Bh + e + 2) = __floats2half2_rn(0.f, 0.f);
    }
}

// ------------------------------------------------------------------
// mma / ldmatrix / cp.async helpers
// ------------------------------------------------------------------
__device__ __forceinline__ void cp_async16(uint32_t dst, const void* src)
{
    asm volatile("cp.async.cg.shared.global [%0], [%1], 16;" :: "r"(dst), "l"(src));
}
__device__ __forceinline__ void cp_commit()
{
    asm volatile("cp.async.commit_group;");
}
__device__ __forceinline__ void cp_wait_all()
{
    asm volatile("cp.async.wait_group 0;");
}
__device__ __forceinline__ void ldsm_x4(uint32_t& r0, uint32_t& r1,
                                        uint32_t& r2, uint32_t& r3, uint32_t addr)
{
    asm volatile("ldmatrix.sync.aligned.m8n8.x4.shared.b16 {%0,%1,%2,%3}, [%4];"
                 : "=r"(r0), "=r"(r1), "=r"(r2), "=r"(r3) : "r"(addr));
}
__device__ __forceinline__ void ldsm_x2(uint32_t& r0, uint32_t& r1, uint32_t addr)
{
    asm volatile("ldmatrix.sync.aligned.m8n8.x2.shared.b16 {%0,%1}, [%2];"
                 : "=r"(r0), "=r"(r1) : "r"(addr));
}
__device__ __forceinline__ void mma16816(float& c0, float& c1, float& c2, float& c3,
                                         uint32_t a0, uint32_t a1, uint32_t a2, uint32_t a3,
                                         uint32_t b0, uint32_t b1)
{
    asm volatile("mma.sync.aligned.m16n8k16.row.col.f32.f16.f16.f32 "
                 "{%0,%1,%2,%3}, {%4,%5,%6,%7}, {%8,%9}, {%0,%1,%2,%3};"
                 : "+f"(c0), "+f"(c1), "+f"(c2), "+f"(c3)
                 : "r"(a0), "r"(a1), "r"(a2), "r"(a3), "r"(b0), "r"(b1));
}

__device__ __forceinline__ float fsigm(float x)
{
    x = fminf(fmaxf(x, -30.f), 30.f);
    return __fdividef(1.f, 1.f + __expf(-x));
}
__device__ __forceinline__ float ftanh(float x)
{
    x = fminf(fmaxf(x, -15.f), 15.f);
    float e = __expf(2.f * x);
    return __fdividef(e - 1.f, e + 1.f);
}

// ------------------------------------------------------------------
// kernel 4: sequential LSTM via HMMA (persistent, 128 CTAs x 128 thr)
// Per-step additions vs R8: G(t+1) prefetched via cp.async into a
// double-buffered raw sG region during step t (off the critical path).
// SMEM: sW 16x520h (16640B) | sH 32x520h (33280B) | sG raw 2x2048B
// ------------------------------------------------------------------
#define SW_OFF 0
#define SH_OFF 16640
#define SG_OFF 49920
#define LSTM_SMEM 54016

__global__ void __launch_bounds__(128, 1) k_lstm()
{
    extern __shared__ __align__(16) char smem[];
    uint32_t sbase = (uint32_t)__cvta_generic_to_shared(smem);
    __shared__ unsigned sGen;

    const int tid  = threadIdx.x;
    const int lane = tid & 31;
    const int w    = tid >> 5;          // warp 0..3
    const int p    = blockIdx.x;        // 0..127

    // ---- load W slice (16 rows x 512 halves) into SMEM ----
    for (int i = 0; i < 8; i++) {
        int idx = tid + i * 128;        // 0..1023
        int lr = idx >> 6, seg = idx & 63;
        int n  = (lr >> 2) * HH + p * 4 + (lr & 3);
        cp_async16(sbase + SW_OFF + lr * 1040 + seg * 16,
                   g_Whh16 + (size_t)n * HH + seg * 8);
    }
    cp_commit(); cp_wait_all();

    // ---- c state in registers (lanes 0-15 of each warp) ----
    const int q    = lane >> 2;                 // 0..3 valid for lane<16
    const int colb = w * 8 + (lane & 3) * 2;    // batch pair base
    float cs0 = 0.f, cs1 = 0.f;
    if (lane < 16) {
        cs0 = g_c0[colb * HH + p * 4 + q];
        cs1 = g_c0[(colb + 1) * HH + p * 4 + q];
    }

    if (tid == 0) sGen = g_bar_gen;
    __syncthreads();
    const unsigned base_gen = sGen;

    // ldmatrix lane offsets
    const int amat = lane >> 3;
    const uint32_t aoff = sbase + SW_OFF
        + (uint32_t)(((amat & 1) * 8 + (lane & 7)) * 1040 + ((amat >> 1) * 8) * 2);
    const uint32_t boff = sbase + SH_OFF
        + (uint32_t)((w * 8 + (lane & 7)) * 1040 + (lane >> 3) * 16);

    // G staging identity for this thread
    const int gb_b = tid & 31, gb_g = tid >> 5;

    // ---- prologue: prefetch G(0) into buffer 0 ----
    cp_async16(sbase + SG_OFF + (gb_g * 32 + gb_b) * 16,
               g_G + (size_t)(0 * BQ + gb_b) * G4 + gb_g * HH + p * 4);
    cp_commit();                                   // pending: {G(0)}

    for (int t = 0; t < TT; t++) {
        // ---- stage this warp's 8 h rows (critical path) ----
        {
            const __half* hsrc = g_h16 + (size_t)t * (BQ * HH);
            #pragma unroll
            for (int j = 0; j < 16; j++) {
                int idx = lane + j * 32;        // 0..511
                int row = idx >> 6, seg = idx & 63;
                cp_async16(sbase + SH_OFF + (w * 8 + row) * 1040 + seg * 16,
                           hsrc + (size_t)(w * 8 + row) * HH + seg * 8);
            }
            cp_commit();                        // group h(t)
        }
        // ---- prefetch G(t+1) (off critical path) ----
        if (t + 1 < TT) {
            cp_async16(sbase + SG_OFF + ((t + 1) & 1) * 2048 + (gb_g * 32 + gb_b) * 16,
                       g_G + (size_t)((t + 1) * BQ + gb_b) * G4 + gb_g * HH + p * 4);
            cp_commit();                        // group G(t+1)
            asm volatile("cp.async.wait_group 1;");   // h(t), G(t) done
        } else {
            asm volatile("cp.async.wait_group 0;");
        }
        __syncwarp();

        // ---- MMA: 32 k-steps, 4 interleaved accumulator sets ----
        float acc[4][4];
        #pragma unroll
        for (int s = 0; s < 4; s++)
            { acc[s][0] = 0.f; acc[s][1] = 0.f; acc[s][2] = 0.f; acc[s][3] = 0.f; }

        #pragma unroll
        for (int i = 0; i < 16; i++) {
            uint32_t b0, b1, b2, b3;
            ldsm_x4(b0, b1, b2, b3, boff + i * 64);
            uint32_t a0, a1, a2, a3;
            ldsm_x4(a0, a1, a2, a3, aoff + (2 * i) * 32);
            int s0 = (2 * i) & 3;
            mma16816(acc[s0][0], acc[s0][1], acc[s0][2], acc[s0][3],
                     a0, a1, a2, a3, b0, b1);
            ldsm_x4(a0, a1, a2, a3, aoff + (2 * i + 1) * 32);
            int s1 = (2 * i + 1) & 3;
            mma16816(acc[s1][0], acc[s1][1], acc[s1][2], acc[s1][3],
                     a0, a1, a2, a3, b2, b3);
        }
        float g0 = (acc[0][0] + acc[1][0]) + (acc[2][0] + acc[3][0]);
        float g1 = (acc[0][1] + acc[1][1]) + (acc[2][1] + acc[3][1]);
        float g2 = (acc[0][2] + acc[1][2]) + (acc[2][2] + acc[3][2]);
        float g3 = (acc[0][3] + acc[1][3]) + (acc[2][3] + acc[3][3]);

        __syncthreads();   // all threads' G(t) copies visible

        // ---- add G (raw layout: sG[(gate*32+b)*4 + q]) ----
        const float* sGc = (const float*)(smem + SG_OFF + (t & 1) * 2048);
        {
            int r0 = lane >> 2;                 // 0..7
            int gg = r0 >> 2, qq = r0 & 3;      // gate base (0 or 1), q
            g0 += sGc[(gg * 32 + colb) * 4 + qq];
            g1 += sGc[(gg * 32 + colb + 1) * 4 + qq];
            g2 += sGc[((gg + 2) * 32 + colb) * 4 + qq];
            g3 += sGc[((gg + 2) * 32 + colb + 1) * 4 + qq];
        }

        // ---- exchange f/o (lanes 16-31) -> i/g holders (lanes 0-15) ----
        float f0 = __shfl_xor_sync(0xffffffffu, g0, 16);
        float f1 = __shfl_xor_sync(0xffffffffu, g1, 16);
        float o0 = __shfl_xor_sync(0xffffffffu, g2, 16);
        float o1 = __shfl_xor_sync(0xffffffffu, g3, 16);

        if (lane < 16) {
            float i0 = fsigm(g0), i1 = fsigm(g1);
            float t0 = ftanh(g2), t1 = ftanh(g3);
            float F0 = fsigm(f0), F1 = fsigm(f1);
            float O0 = fsigm(o0), O1 = fsigm(o1);
            cs0 = F0 * cs0 + i0 * t0;
            cs1 = F1 * cs1 + i1 * t1;
            float h0 = O0 * ftanh(cs0);
            float h1 = O1 * ftanh(cs1);
            size_t hb = (size_t)(t + 1) * (BQ * HH) + p * 4 + q;
            g_h16[hb + (size_t)colb * HH]       = __float2half_rn(h0);
            g_h16[hb + (size_t)(colb + 1) * HH] = __float2half_rn(h1);
        }

        // ---- grid barrier ----
        __threadfence();
        __syncthreads();
        if (tid == 0) {
            unsigned target = base_gen + (unsigned)(t + 1);
            unsigned arr = atomicAdd(&g_bar_count, 1u);
            if (arr == 127u) {
                g_bar_count = 0u;
                __threadfence();
                atomicExch(&g_bar_gen, target);
            } else {
                volatile unsigned* vg = &g_bar_gen;
                while (*vg < target) { }
            }
            __threadfence();
        }
        __syncthreads();
    }
}

#define MMA_SMEM_BUF 20480           // A(10240) + B(10240) per buffer

// ------------------------------------------------------------------
// kernel 5: G = E @ Wih^T + base  (fp16 HMMA, K=256)
// ------------------------------------------------------------------
__device__ __forceinline__ void g_load_tile(
    int kt, int buf, int tid, int mtb, int ntb, uint32_t sbase)
{
    const int k0 = kt * 32;
    const uint32_t abase = sbase + buf * MMA_SMEM_BUF;
    const uint32_t bbase = abase + 10240;
    #pragma unroll
    for (int i = 0; i < 2; i++) {
        int ch  = tid + i * 256;
        int row = ch >> 2, kc = ch & 3;
        cp_async16(abase + row * 80 + kc * 16,
                   g_E + (size_t)(mtb * 128 + row) * EE + k0 + kc * 8);
        cp_async16(bbase + row * 80 + kc * 16,
                   g_Wih16 + (size_t)(ntb * 128 + row) * EE + k0 + kc * 8);
    }
    cp_commit();
}

__global__ void __launch_bounds__(256) k_G_mma()
{
    __shared__ __align__(16) unsigned char smem[2 * MMA_SMEM_BUF];
    const int tid  = threadIdx.x;
    const int lane = tid & 31;
    const int warp = tid >> 5;
    const int ntb  = blockIdx.x;     // 0..15
    const int mtb  = blockIdx.y;     // 0..31

    const int wm = (warp >> 2) * 64;
    const int wn = (warp & 3) * 32;

    uint32_t sbase = (uint32_t)__cvta_generic_to_shared(smem);

    float acc[4][4][4];
    #pragma unroll
    for (int i = 0; i < 4; i++)
        #pragma unroll
        for (int j = 0; j < 4; j++) {
            acc[i][j][0] = 0.f; acc[i][j][1] = 0.f;
            acc[i][j][2] = 0.f; acc[i][j][3] = 0.f;
        }

    const int amat  = lane >> 3;
    const uint32_t a_lane_off = (uint32_t)((wm + (amat & 1) * 8 + (lane & 7)) * 80
                                           + ((amat >> 1) * 8) * 2);
    const int blane = lane & 15;
    const uint32_t b_lane_off = (uint32_t)(10240 + (wn + (blane & 7)) * 80
                                           + ((blane >> 3) * 8) * 2);

    const int NKT = 8;                         // 256 / 32
    g_load_tile(0, 0, tid, mtb, ntb, sbase);

    for (int kt = 0; kt < NKT; kt++) {
        if (kt + 1 < NKT) {
            g_load_tile(kt + 1, (kt + 1) & 1, tid, mtb, ntb, sbase);
            asm volatile("cp.async.wait_group 1;");
        } else {
            asm volatile("cp.async.wait_group 0;");
        }
        __syncthreads();

        const uint32_t abase = sbase + (kt & 1) * MMA_SMEM_BUF;
        #pragma unroll
        for (int k16 = 0; k16 < 2; k16++) {
            uint32_t af[4][4];
            uint32_t bf[4][2];
            #pragma unroll
            for (int mt = 0; mt < 4; mt++) {
                uint32_t ad = abase + a_lane_off + mt * (16 * 80) + k16 * 32;
                ldsm_x4(af[mt][0], af[mt][1], af[mt][2], af[mt][3], ad);
            }
            #pragma unroll
            for (int nt = 0; nt < 4; nt++) {
                uint32_t bd = abase + b_lane_off + nt * (8 * 80) + k16 * 32;
                ldsm_x2(bf[nt][0], bf[nt][1], bd);
            }
            #pragma unroll
            for (int mt = 0; mt < 4; mt++)
                #pragma unroll
                for (int nt = 0; nt < 4; nt++)
                    mma16816(acc[mt][nt][0], acc[mt][nt][1],
                             acc[mt][nt][2], acc[mt][nt][3],
                             af[mt][0], af[mt][1], af[mt][2], af[mt][3],
                             bf[nt][0], bf[nt][1]);
        }
        __syncthreads();
    }

    #pragma unroll
    for (int mt = 0; mt < 4; mt++) {
        #pragma unroll
        for (int nt = 0; nt < 4; nt++) {
            int col = ntb * 128 + wn + nt * 8 + (lane & 3) * 2;
            int m0 = mtb * 128 + wm + mt * 16 + (lane >> 2);
            float2 bs0 = *(const float2*)&g_base[(m0 & 31) * G4 + col];
            float2 v0 = { acc[mt][nt][0] + bs0.x, acc[mt][nt][1] + bs0.y };
            *(float2*)&g_G[(size_t)m0 * G4 + col] = v0;
            int m1 = m0 + 8;
            float2 bs1 = *(const float2*)&g_base[(m1 & 31) * G4 + col];
            float2 v1 = { acc[mt][nt][2] + bs1.x, acc[mt][nt][3] + bs1.y };
            *(float2*)&g_G[(size_t)m1 * G4 + col] = v1;
        }
    }
}

// ------------------------------------------------------------------
// kernel 5b: base = X @ Wihb^T + b_ih + b_hh  (fp16 HMMA, M=128 pad, K=1024)
// ------------------------------------------------------------------
__device__ __forceinline__ void base_load_tile(
    int kt, int buf, int tid, int ntb, uint32_t sbase)
{
    const int k0 = kt * 32;
    const uint32_t abase = sbase + buf * MMA_SMEM_BUF;
    const uint32_t bbase = abase + 10240;
    #pragma unroll
    for (int i = 0; i < 2; i++) {
        int ch  = tid + i * 256;
        int row = ch >> 2, kc = ch & 3;
        cp_async16(abase + row * 80 + kc * 16,
                   g_X16 + (size_t)row * 1024 + k0 + kc * 8);
        cp_async16(bbase + row * 80 + kc * 16,
                   g_Wihb + (size_t)(ntb * 128 + row) * 1024 + k0 + kc * 8);
    }
    cp_commit();
}

__global__ void __launch_bounds__(256) k_base_mma(const float* __restrict__ b_ih,
                                                  const float* __restrict__ b_hh)
{
    __shared__ __align__(16) unsigned char smem[2 * MMA_SMEM_BUF];
    const int tid  = threadIdx.x;
    const int lane = tid & 31;
    const int warp = tid >> 5;
    const int ntb  = blockIdx.x;     // 0..15

    const int wm = (warp >> 2) * 64;
    const int wn = (warp & 3) * 32;

    uint32_t sbase = (uint32_t)__cvta_generic_to_shared(smem);

    float acc[4][4][4];
    #pragma unroll
    for (int i = 0; i < 4; i++)
        #pragma unroll
        for (int j = 0; j < 4; j++) {
            acc[i][j][0] = 0.f; acc[i][j][1] = 0.f;
            acc[i][j][2] = 0.f; acc[i][j][3] = 0.f;
        }

    const int amat  = lane >> 3;
    const uint32_t a_lane_off = (uint32_t)((wm + (amat & 1) * 8 + (lane & 7)) * 80
                                           + ((amat >> 1) * 8) * 2);
    const int blane = lane & 15;
    const uint32_t b_lane_off = (uint32_t)(10240 + (wn + (blane & 7)) * 80
                                           + ((blane >> 3) * 8) * 2);

    const int NKT = 32;                        // 1024 / 32
    base_load_tile(0, 0, tid, ntb, sbase);

    for (int kt = 0; kt < NKT; kt++) {
        if (kt + 1 < NKT) {
            base_load_tile(kt + 1, (kt + 1) & 1, tid, ntb, sbase);
            asm volatile("cp.async.wait_group 1;");
        } else {
            asm volatile("cp.async.wait_group 0;");
        }
        __syncthreads();

        const uint32_t abase = sbase + (kt & 1) * MMA_SMEM_BUF;
        #pragma unroll
        for (int k16 = 0; k16 < 2; k16++) {
            uint32_t af[4][4];
            uint32_t bf[4][2];
            #pragma unroll
            for (int mt = 0; mt < 4; mt++) {
                uint32_t ad = abase + a_lane_off + mt * (16 * 80) + k16 * 32;
                ldsm_x4(af[mt][0], af[mt][1], af[mt][2], af[mt][3], ad);
            }
            #pragma unroll
            for (int nt = 0; nt < 4; nt++) {
                uint32_t bd = abase + b_lane_off + nt * (8 * 80) + k16 * 32;
                ldsm_x2(bf[nt][0], bf[nt][1], bd);
            }
            #pragma unroll
            for (int mt = 0; mt < 4; mt++)
                #pragma unroll
                for (int nt = 0; nt < 4; nt++)
                    mma16816(acc[mt][nt][0], acc[mt][nt][1],
                             acc[mt][nt][2], acc[mt][nt][3],
                             af[mt][0], af[mt][1], af[mt][2], af[mt][3],
                             bf[nt][0], bf[nt][1]);
        }
        __syncthreads();
    }

    #pragma unroll
    for (int mt = 0; mt < 4; mt++) {
        #pragma unroll
        for (int nt = 0; nt < 4; nt++) {
            int col = ntb * 128 + wn + nt * 8 + (lane & 3) * 2;
            float bb0 = __ldg(b_ih + col) + __ldg(b_hh + col);
            float bb1 = __ldg(b_ih + col + 1) + __ldg(b_hh + col + 1);
            int m0 = wm + mt * 16 + (lane >> 2);
            if (m0 < BQ) {
                float2 v0 = { acc[mt][nt][0] + bb0, acc[mt][nt][1] + bb1 };
                *(float2*)&g_base[m0 * G4 + col] = v0;
            }
            int m1 = m0 + 8;
            if (m1 < BQ) {
                float2 v1 = { acc[mt][nt][2] + bb0, acc[mt][nt][3] + bb1 };
                *(float2*)&g_base[m1 * G4 + col] = v1;
            }
        }
    }
}

// ------------------------------------------------------------------
// kernel 6: logits via fp16 HMMA, single pass (K = 512)
// ------------------------------------------------------------------
__device__ __forceinline__ void logits_load_tile(
    int kt, int buf, int tid, int mtb, int ntb, uint32_t sbase)
{
    const int k0 = kt * 32;
    const __half* A = g_h16 + BQ * HH;
    const uint32_t abase = sbase + buf * MMA_SMEM_BUF;
    const uint32_t bbase = abase + 10240;
    #pragma unroll
    for (int i = 0; i < 2; i++) {
        int ch  = tid + i * 256;
        int row = ch >> 2, kc = ch & 3;
        cp_async16(abase + row * 80 + kc * 16,
                   A + (size_t)(mtb * 128 + row) * HH + k0 + kc * 8);
        cp_async16(bbase + row * 80 + kc * 16,
                   g_Bh + (size_t)(ntb * 128 + row) * HH + k0 + kc * 8);
    }
    cp_commit();
}

__global__ void __launch_bounds__(256) k_logits_mma(const float* __restrict__ bv,
                                                    float* __restrict__ out)
{
    __shared__ __align__(16) unsigned char smem[2 * MMA_SMEM_BUF];
    const int tid  = threadIdx.x;
    const int lane = tid & 31;
    const int warp = tid >> 5;
    const int ntb  = blockIdx.x;     // 0..78
    const int mtb  = blockIdx.y;     // 0..31

    const int wm = (warp >> 2) * 64;
    const int wn = (warp & 3) * 32;

    uint32_t sbase = (uint32_t)__cvta_generic_to_shared(smem);

    float acc[4][4][4];
    #pragma unroll
    for (int i = 0; i < 4; i++)
        #pragma unroll
        for (int j = 0; j < 4; j++) {
            acc[i][j][0] = 0.f; acc[i][j][1] = 0.f;
            acc[i][j][2] = 0.f; acc[i][j][3] = 0.f;
        }

    const int amat  = lane >> 3;
    const uint32_t a_lane_off = (uint32_t)((wm + (amat & 1) * 8 + (lane & 7)) * 80
                                           + ((amat >> 1) * 8) * 2);
    const int blane = lane & 15;
    const uint32_t b_lane_off = (uint32_t)(10240 + (wn + (blane & 7)) * 80
                                           + ((blane >> 3) * 8) * 2);

    const int NKT = 16;                        // 512 / 32
    logits_load_tile(0, 0, tid, mtb, ntb, sbase);

    for (int kt = 0; kt < NKT; kt++) {
        if (kt + 1 < NKT) {
            logits_load_tile(kt + 1, (kt + 1) & 1, tid, mtb, ntb, sbase);
            asm volatile("cp.async.wait_group 1;");
        } else {
            asm volatile("cp.async.wait_group 0;");
        }
        __syncthreads();

        const uint32_t abase = sbase + (kt & 1) * MMA_SMEM_BUF;
        #pragma unroll
        for (int k16 = 0; k16 < 2; k16++) {
            uint32_t af[4][4];
            uint32_t bf[4][2];
            #pragma unroll
            for (int mt = 0; mt < 4; mt++) {
                uint32_t ad = abase + a_lane_off + mt * (16 * 80) + k16 * 32;
                ldsm_x4(af[mt][0], af[mt][1], af[mt][2], af[mt][3], ad);
            }
            #pragma unroll
            for (int nt = 0; nt < 4; nt++) {
                uint32_t bd = abase + b_lane_off + nt * (8 * 80) + k16 * 32;
                ldsm_x2(bf[nt][0], bf[nt][1], bd);
            }
            #pragma unroll
            for (int mt = 0; mt < 4; mt++)
                #pragma unroll
                for (int nt = 0; nt < 4; nt++)
                    mma16816(acc[mt][nt][0], acc[mt][nt][1],
                             acc[mt][nt][2], acc[mt][nt][3],
                             af[mt][0], af[mt][1], af[mt][2], af[mt][3],
                             bf[nt][0], bf[nt][1]);
        }
        __syncthreads();
    }

    #pragma unroll
    for (int mt = 0; mt < 4; mt++) {
        #pragma unroll
        for (int nt = 0; nt < 4; nt++) {
            int col = ntb * 128 + wn + nt * 8 + (lane & 3) * 2;
            if (col < VV) {
                float bb0 = __ldg(bv + col);
                float bb1 = __ldg(bv + col + 1);
                int m0 = mtb * 128 + wm + mt * 16 + (lane >> 2);
                int bI = m0 & 31, tI = m0 >> 5;
                float2 v0 = { acc[mt][nt][0] + bb0, acc[mt][nt][1] + bb1 };
                *(float2*)(out + (size_t)bI * TT * VV + (size_t)tI * VV + col) = v0;
                int m1 = m0 + 8;
                bI = m1 & 31; tI = m1 >> 5;
                float2 v1 = { acc[mt][nt][2] + bb0, acc[mt][nt][3] + bb1 };
                *(float2*)(out + (size_t)bI * TT * VV + (size_t)tI * VV + col) = v1;
            }
        }
    }
}

// ------------------------------------------------------------------
extern "C" void kernel_launch(void* const* d_in, const int* in_sizes, int n_in,
                              void* d_out, int out_size)
{
    const float* tv    = (const float*)d_in[0];
    const int*   texts = (const int*)  d_in[1];
    const int*   start = (const int*)  d_in[3];
    const float* emb   = (const float*)d_in[4];
    const float* W_ih  = (const float*)d_in[5];
    const float* b_ih  = (const float*)d_in[6];
    const float* W_hh  = (const float*)d_in[7];
    const float* b_hh  = (const float*)d_in[8];
    const float* Wo_w  = (const float*)d_in[9];
    const float* Wo_b  = (const float*)d_in[10];
    const float* Wh_w  = (const float*)d_in[11];
    const float* Wh_b  = (const float*)d_in[12];
    const float* Wc_w  = (const float*)d_in[13];
    const float* Wc_b  = (const float*)d_in[14];
    const float* Wv_w  = (const float*)d_in[15];
    const float* Wv_b  = (const float*)d_in[16];
    float* out = (float*)d_out;

    cudaFuncSetAttribute(k_lstm, cudaFuncAttributeMaxDynamicSharedMemorySize, LSTM_SMEM);

    k_init<<<6144, 256>>>(tv, Wo_w, Wo_b, Wh_w, Wh_b, Wc_w, Wc_b);
    k_gather<<<TT * BQ, 64>>>(emb, texts, start);
    k_convW<<<(G4 * EE) / 1024, 256>>>(W_ih);
    k_convWb<<<(G4 * 1024) / 1024, 256>>>(W_ih);
    k_convWhh<<<(G4 * HH) / 1024, 256>>>(W_hh);
    k_convB<<<(VPAD * HH) / 1024, 256>>>(Wv_w);
    k_packX<<<(BQ * 1024) / 512, 256>>>(tv);
    k_base_mma<<<16, 256>>>(b_ih, b_hh);
    k_G_mma<<<dim3(G4 / 128, (TT * BQ) / 128), 256>>>();
    k_lstm<<<128, 128, LSTM_SMEM>>>();
    k_logits_mma<<<dim3(VPAD / 128, (TT * BQ) / 128), 256>>>(Wv_b, out);
}